// round 7
// baseline (speedup 1.0000x reference)
#include <cuda_runtime.h>
#include <cstdint>

#define B_    8
#define V_    4096
#define P_    32
#define CIN   64
#define COUT  128
#define BV    (B_ * V_)      // 32768
#define K2    512

// ypow [BV][K2] scratch, k = c*8 + r*4 + l (matches W flattening), tf32 bits.
__device__ float g_ypow[(size_t)BV * K2];
// W pre-converted to tf32 bits (filled by first 1024 CTAs of ypow_kernel)
__device__ uint32_t g_W[(size_t)COUT * K2];

__device__ __forceinline__ uint32_t f2tf32(float x) {
    uint32_t r;
    asm("cvt.rna.tf32.f32 %0, %1;" : "=r"(r) : "f"(x));
    return r;
}

__device__ __forceinline__ void mma_tf32(float& d0, float& d1, float& d2, float& d3,
                                         uint32_t a0, uint32_t a1, uint32_t a2, uint32_t a3,
                                         uint32_t b0, uint32_t b1) {
    asm volatile(
        "mma.sync.aligned.m16n8k8.row.col.f32.tf32.tf32.f32 "
        "{%0,%1,%2,%3}, {%4,%5,%6,%7}, {%8,%9}, {%0,%1,%2,%3};"
        : "+f"(d0), "+f"(d1), "+f"(d2), "+f"(d3)
        : "r"(a0), "r"(a1), "r"(a2), "r"(a3), "r"(b0), "r"(b1));
}

__device__ __forceinline__ void ldsm_x4(uint32_t* r, uint32_t addr) {
    asm volatile("ldmatrix.sync.aligned.m8n8.x4.shared.b16 {%0,%1,%2,%3}, [%4];"
        : "=r"(r[0]), "=r"(r[1]), "=r"(r[2]), "=r"(r[3]) : "r"(addr));
}

__device__ __forceinline__ float sqclip(float x) {
    return sqrtf(fmaxf(x, 1e-4f));
}

__device__ __forceinline__ uint32_t smem_u32(const void* p) {
    return (uint32_t)__cvta_generic_to_shared(p);
}

__device__ __forceinline__ void cp_async16(uint32_t dst, const void* src) {
    asm volatile("cp.async.cg.shared.global [%0], [%1], 16;" :: "r"(dst), "l"(src));
}

// ---------------------------------------------------------------------------
// Kernel 1: CTA = 64 threads = 2 warps = ONE bv.
// D[c=64][rn=32] = S^T(64c x 32p) * ck(32p x 32rn); warp h owns c-half h.
// A-frags from own gathered-S half, B-frags from shared ck -- scalar LDS,
// conflict-free. Epilogue entirely in registers: square, predicated l-bucket
// partials, quad butterfly shuffles, coalesced float4 STG. No smem bounce.
// First 1024 CTAs also convert W -> tf32 for kernel 2.
// ---------------------------------------------------------------------------
#define CK_STR 40
#define SH_STR 40

__global__ __launch_bounds__(64, 12)
void ypow_kernel(const float* __restrict__ signal,
                 const int*   __restrict__ pidx,
                 const float* __restrict__ convk,
                 const float* __restrict__ W)
{
    __shared__ uint32_t sCK[32 * CK_STR];      // ck [p][rn] pad 40
    __shared__ uint32_t sSh[2][32 * SH_STR];   // per-warp S half [p][c'] pad 40

    const int tid  = threadIdx.x;
    const int warp = tid >> 5;      // c-half
    const int lane = tid & 31;
    const int bv   = blockIdx.x;
    const int g    = lane >> 2;
    const int tig  = lane & 3;

    if (blockIdx.x < 1024)
        g_W[blockIdx.x * 64 + tid] = f2tf32(W[blockIdx.x * 64 + tid]);

    // lane p = lane: gathered signal row base (in floats)
    const int2 ip = ((const int2*)pidx)[bv * P_ + lane];
    const int base = (ip.x * V_ + ip.y) * CIN;

    // Stage ck [p][rn]: 256 float4, both warps, coalesced
    {
        const float4* ck4 = (const float4*)(convk + (size_t)bv * 1024);
        #pragma unroll
        for (int j = 0; j < 4; ++j) {
            int f = j * 64 + tid;
            float4 v = ck4[f];
            int p = f >> 3, q = f & 7;
            uint4 u;
            u.x = f2tf32(v.x); u.y = f2tf32(v.y); u.z = f2tf32(v.z); u.w = f2tf32(v.w);
            *(uint4*)&sCK[p * CK_STR + q * 4] = u;
        }
    }
    // Stage own S half [p][c' 0..31] (global c = warp*32 + c')
    {
        uint32_t* sS = sSh[warp];
        #pragma unroll
        for (int j = 0; j < 8; ++j) {
            int f = j * 32 + lane;
            int p = f >> 3, q = f & 7;
            int bp = __shfl_sync(0xffffffffu, base, p);
            float4 v = *(const float4*)(signal + bp + warp * 32 + q * 4);
            uint4 u;
            u.x = f2tf32(v.x); u.y = f2tf32(v.y); u.z = f2tf32(v.z); u.w = f2tf32(v.w);
            *(uint4*)&sS[p * SH_STR + q * 4] = u;
        }
    }
    __syncthreads();

    // Warp computes D[its 32 c'][rn=32]: 2 mt(c) x 4 nt(rn) x 4 ks
    const uint32_t* sS = sSh[warp];
    float acc[2][4][4];
    #pragma unroll
    for (int i = 0; i < 2; ++i)
        #pragma unroll
        for (int j = 0; j < 4; ++j)
            #pragma unroll
            for (int e = 0; e < 4; ++e) acc[i][j][e] = 0.0f;

    #pragma unroll
    for (int ks = 0; ks < 4; ++ks) {
        const int k0 = ks * 8;
        uint32_t a[2][4];
        #pragma unroll
        for (int mt = 0; mt < 2; ++mt) {
            a[mt][0] = sS[(k0 + tig)     * SH_STR + mt * 16 + g];
            a[mt][1] = sS[(k0 + tig)     * SH_STR + mt * 16 + g + 8];
            a[mt][2] = sS[(k0 + tig + 4) * SH_STR + mt * 16 + g];
            a[mt][3] = sS[(k0 + tig + 4) * SH_STR + mt * 16 + g + 8];
        }
        #pragma unroll
        for (int nt = 0; nt < 4; ++nt) {
            uint32_t b0 = sCK[(k0 + tig)     * CK_STR + nt * 8 + g];
            uint32_t b1 = sCK[(k0 + tig + 4) * CK_STR + nt * 8 + g];
            mma_tf32(acc[0][nt][0], acc[0][nt][1], acc[0][nt][2], acc[0][nt][3],
                     a[0][0], a[0][1], a[0][2], a[0][3], b0, b1);
            mma_tf32(acc[1][nt][0], acc[1][nt][1], acc[1][nt][2], acc[1][nt][3],
                     a[1][0], a[1][1], a[1][2], a[1][3], b0, b1);
        }
    }

    // Register epilogue.  Lane (g,tig), tile mt:
    //   acc[mt][nt][0,1] = D[c = C+g   ][rn = nt*8 + 2tig + {0,1}]
    //   acc[mt][nt][2,3] = D[c = C+g+8 ][  same cols ]           (C = warp*32+mt*16)
    // rn = r*16 + n;  nt(0,1)->r=0, nt(2,3)->r=1.
    // n l-buckets: {0}->l0, {1..3}->l1, {4..8}->l2, {9..15}->l3.
    float4* outp = (float4*)g_ypow + (size_t)bv * 128;
    #pragma unroll
    for (int mt = 0; mt < 2; ++mt) {
        float lv[2][2][4];   // [h(row 0:g,1:g+8)][r][l]
        #pragma unroll
        for (int h = 0; h < 2; ++h) {
            #pragma unroll
            for (int r = 0; r < 2; ++r) {
                // even n-tile (n = 2tig,2tig+1), odd n-tile (n = 8+2tig, 9+2tig)
                float e0 = acc[mt][2 * r][2 * h],     e1 = acc[mt][2 * r][2 * h + 1];
                float o0 = acc[mt][2 * r + 1][2 * h], o1 = acc[mt][2 * r + 1][2 * h + 1];
                float qe0 = e0 * e0, qe1 = e1 * e1;
                float qo0 = o0 * o0, qo1 = o1 * o1;
                float se = qe0 + qe1, so = qo0 + qo1;
                // per-tig bucket contributions
                float p0 = (tig == 0) ? qe0 : 0.0f;
                float p1 = (tig == 0) ? qe1 : ((tig == 1) ? se : 0.0f);
                float p2 = (tig == 0) ? qo0 : ((tig >= 2) ? se : 0.0f);
                float p3 = (tig == 0) ? qo1 : so;
                // quad butterfly over tig
                p0 += __shfl_xor_sync(0xffffffffu, p0, 1);
                p1 += __shfl_xor_sync(0xffffffffu, p1, 1);
                p2 += __shfl_xor_sync(0xffffffffu, p2, 1);
                p3 += __shfl_xor_sync(0xffffffffu, p3, 1);
                p0 += __shfl_xor_sync(0xffffffffu, p0, 2);
                p1 += __shfl_xor_sync(0xffffffffu, p1, 2);
                p2 += __shfl_xor_sync(0xffffffffu, p2, 2);
                p3 += __shfl_xor_sync(0xffffffffu, p3, 2);
                lv[h][r][0] = p0; lv[h][r][1] = p1;
                lv[h][r][2] = p2; lv[h][r][3] = p3;
            }
        }
        // Lane tig takes (h = tig>>1, r = tig&1); coalesced float4 store.
        const bool hb = (tig & 2), rb = (tig & 1);
        float s0 = hb ? (rb ? lv[1][1][0] : lv[1][0][0]) : (rb ? lv[0][1][0] : lv[0][0][0]);
        float s1 = hb ? (rb ? lv[1][1][1] : lv[1][0][1]) : (rb ? lv[0][1][1] : lv[0][0][1]);
        float s2 = hb ? (rb ? lv[1][1][2] : lv[1][0][2]) : (rb ? lv[0][1][2] : lv[0][0][2]);
        float s3 = hb ? (rb ? lv[1][1][3] : lv[1][0][3]) : (rb ? lv[0][1][3] : lv[0][0][3]);
        float4 o;
        o.x = __uint_as_float(f2tf32(sqclip(s0)));
        o.y = __uint_as_float(f2tf32(sqclip(s1)));
        o.z = __uint_as_float(f2tf32(sqclip(s2)));
        o.w = __uint_as_float(f2tf32(sqclip(s3)));
        outp[warp * 64 + mt * 32 + g * 2 + (tig >> 1) * 16 + (tig & 1)] = o;
    }
}

// ---------------------------------------------------------------------------
// Kernel 2: out = ypow * W^T + bias, relu.  CTA 128 thr, tile 64m x 128n,
// 4-stage cp.async pipeline (kT=16, 1 sync/iter), XOR-swizzled tiles,
// ldmatrix.x4 fragment loads.  Warp = 32m x 64n.  (unchanged from R6)
// ---------------------------------------------------------------------------
#define KT     16
#define NKT    (K2 / KT)    // 32
#define M_BLK  64
#define N_BLK  128

__device__ __forceinline__ int swz(int row, int c) {
    return row * 16 + ((c ^ ((row >> 1) & 3)) << 2);
}

__global__ __launch_bounds__(128, 4)
void out_gemm_kernel(const float* __restrict__ bias,
                     float* __restrict__ out)
{
    __shared__ uint32_t sA[4][M_BLK * KT];
    __shared__ uint32_t sB[4][N_BLK * KT];

    const int tid  = threadIdx.x;
    const int warp = tid >> 5;
    const int lane = tid & 31;
    const int g    = lane >> 2;
    const int tig  = lane & 3;
    const int wm   = warp >> 1;
    const int wn   = warp & 1;
    const int m0   = blockIdx.x * M_BLK;
    const int quad = lane >> 3;
    const int rin  = lane & 7;

    const uint32_t* yp = (const uint32_t*)g_ypow;

    float acc[2][8][4];
    #pragma unroll
    for (int a = 0; a < 2; ++a)
        #pragma unroll
        for (int b = 0; b < 8; ++b)
            #pragma unroll
            for (int c = 0; c < 4; ++c) acc[a][b][c] = 0.0f;

    auto stage = [&](int kt, int st) {
        #pragma unroll
        for (int i = 0; i < 2; ++i) {
            int id = tid + i * 128;
            int row = id >> 2, c = id & 3;
            cp_async16(smem_u32(&sA[st][swz(row, c)]),
                       yp + (size_t)(m0 + row) * K2 + kt * KT + c * 4);
        }
        #pragma unroll
        for (int i = 0; i < 4; ++i) {
            int id = tid + i * 128;
            int row = id >> 2, c = id & 3;
            cp_async16(smem_u32(&sB[st][swz(row, c)]),
                       g_W + (size_t)row * K2 + kt * KT + c * 4);
        }
        asm volatile("cp.async.commit_group;");
    };

    stage(0, 0);
    stage(1, 1);
    stage(2, 2);

    for (int kt = 0; kt < NKT; ++kt) {
        asm volatile("cp.async.wait_group 2;");
        __syncthreads();
        if (kt + 3 < NKT) stage(kt + 3, (kt + 3) & 3);
        else asm volatile("cp.async.commit_group;");
        const int st = kt & 3;

        #pragma unroll
        for (int ks = 0; ks < 2; ++ks) {
            uint32_t a[2][4];
            #pragma unroll
            for (int mi = 0; mi < 2; ++mi) {
                int row = wm * 32 + mi * 16 + (quad & 1) * 8 + rin;
                int ch  = ks * 2 + (quad >> 1);
                ldsm_x4(a[mi], smem_u32(&sA[st][swz(row, ch)]));
            }
            uint32_t b[4][4];
            #pragma unroll
            for (int p = 0; p < 4; ++p) {
                int row = wn * 64 + p * 16 + (quad >> 1) * 8 + rin;
                int ch  = ks * 2 + (quad & 1);
                ldsm_x4(b[p], smem_u32(&sB[st][swz(row, ch)]));
            }
            #pragma unroll
            for (int p = 0; p < 4; ++p) {
                mma_tf32(acc[0][2*p][0], acc[0][2*p][1], acc[0][2*p][2], acc[0][2*p][3],
                         a[0][0], a[0][1], a[0][2], a[0][3], b[p][0], b[p][1]);
                mma_tf32(acc[0][2*p+1][0], acc[0][2*p+1][1], acc[0][2*p+1][2], acc[0][2*p+1][3],
                         a[0][0], a[0][1], a[0][2], a[0][3], b[p][2], b[p][3]);
                mma_tf32(acc[1][2*p][0], acc[1][2*p][1], acc[1][2*p][2], acc[1][2*p][3],
                         a[1][0], a[1][1], a[1][2], a[1][3], b[p][0], b[p][1]);
                mma_tf32(acc[1][2*p+1][0], acc[1][2*p+1][1], acc[1][2*p+1][2], acc[1][2*p+1][3],
                         a[1][0], a[1][1], a[1][2], a[1][3], b[p][2], b[p][3]);
            }
        }
    }

    #pragma unroll
    for (int nt = 0; nt < 8; ++nt) {
        const int col = wn * 64 + nt * 8 + 2 * tig;
        const float b0 = __ldg(&bias[col]);
        const float b1 = __ldg(&bias[col + 1]);
        #pragma unroll
        for (int mi = 0; mi < 2; ++mi) {
            const int row = m0 + wm * 32 + mi * 16 + g;
            float2 v0, v1;
            v0.x = fmaxf(acc[mi][nt][0] + b0, 0.0f);
            v0.y = fmaxf(acc[mi][nt][1] + b1, 0.0f);
            v1.x = fmaxf(acc[mi][nt][2] + b0, 0.0f);
            v1.y = fmaxf(acc[mi][nt][3] + b1, 0.0f);
            *(float2*)(out + (size_t)row * COUT + col)       = v0;
            *(float2*)(out + (size_t)(row + 8) * COUT + col) = v1;
        }
    }
}

extern "C" void kernel_launch(void* const* d_in, const int* in_sizes, int n_in,
                              void* d_out, int out_size)
{
    const float* signal = (const float*)d_in[0];
    const int*   pidx   = (const int*)  d_in[1];
    const float* convk  = (const float*)d_in[2];
    const float* W      = (const float*)d_in[3];
    const float* bias   = (const float*)d_in[4];
    float* out = (float*)d_out;

    ypow_kernel<<<BV, 64>>>(signal, pidx, convk, W);
    out_gemm_kernel<<<BV / M_BLK, 128>>>(bias, out);
}

// round 8
// speedup vs baseline: 1.2035x; 1.2035x over previous
#include <cuda_runtime.h>
#include <cuda_fp16.h>
#include <cstdint>

#define B_    8
#define V_    4096
#define P_    32
#define CIN   64
#define COUT  128
#define BV    (B_ * V_)      // 32768
#define K2    512

// ypow [BV][K2] scratch in fp16, k = c*8 + r*4 + l (matches W flattening).
__device__ __half g_ypow[(size_t)BV * K2];
// W pre-converted to fp16 (filled by first 1024 CTAs of ypow_kernel)
__device__ __half g_W[(size_t)COUT * K2];

__device__ __forceinline__ uint32_t f2tf32(float x) {
    uint32_t r;
    asm("cvt.rna.tf32.f32 %0, %1;" : "=r"(r) : "f"(x));
    return r;
}

__device__ __forceinline__ void mma_tf32(float& d0, float& d1, float& d2, float& d3,
                                         uint32_t a0, uint32_t a1, uint32_t a2, uint32_t a3,
                                         uint32_t b0, uint32_t b1) {
    asm volatile(
        "mma.sync.aligned.m16n8k8.row.col.f32.tf32.tf32.f32 "
        "{%0,%1,%2,%3}, {%4,%5,%6,%7}, {%8,%9}, {%0,%1,%2,%3};"
        : "+f"(d0), "+f"(d1), "+f"(d2), "+f"(d3)
        : "r"(a0), "r"(a1), "r"(a2), "r"(a3), "r"(b0), "r"(b1));
}

__device__ __forceinline__ void mma_f16(float& d0, float& d1, float& d2, float& d3,
                                        uint32_t a0, uint32_t a1, uint32_t a2, uint32_t a3,
                                        uint32_t b0, uint32_t b1) {
    asm volatile(
        "mma.sync.aligned.m16n8k16.row.col.f32.f16.f16.f32 "
        "{%0,%1,%2,%3}, {%4,%5,%6,%7}, {%8,%9}, {%0,%1,%2,%3};"
        : "+f"(d0), "+f"(d1), "+f"(d2), "+f"(d3)
        : "r"(a0), "r"(a1), "r"(a2), "r"(a3), "r"(b0), "r"(b1));
}

__device__ __forceinline__ void ldsm_x4(uint32_t* r, uint32_t addr) {
    asm volatile("ldmatrix.sync.aligned.m8n8.x4.shared.b16 {%0,%1,%2,%3}, [%4];"
        : "=r"(r[0]), "=r"(r[1]), "=r"(r[2]), "=r"(r[3]) : "r"(addr));
}

__device__ __forceinline__ float sqclip(float x) {
    return sqrtf(fmaxf(x, 1e-4f));
}

__device__ __forceinline__ uint32_t smem_u32(const void* p) {
    return (uint32_t)__cvta_generic_to_shared(p);
}

__device__ __forceinline__ void cp_async16(uint32_t dst, const void* src) {
    asm volatile("cp.async.cg.shared.global [%0], [%1], 16;" :: "r"(dst), "l"(src));
}

// ---------------------------------------------------------------------------
// Kernel 1 (R6 structure): CTA = 64 threads = 2 warps = ONE bv.
// D[m=rn 32][n=c' 32 per warp] = ck^T * S-half, tf32 mma, smem-staged.
// Epilogue: acc -> sY[c'][rn] bounce; one lane per c' reads its 32-value
// column (8x LDS.128, conflict-free), computes 8 l-sums, sqrt, packs 8 fp16,
// single coalesced uint4 store. First 1024 CTAs convert W -> fp16.
// ---------------------------------------------------------------------------
#define CK_STR 40
#define SH_STR 40
#define SY_STR 36

__global__ __launch_bounds__(64, 14)
void ypow_kernel(const float* __restrict__ signal,
                 const int*   __restrict__ pidx,
                 const float* __restrict__ convk,
                 const float* __restrict__ W)
{
    __shared__ uint32_t sCK[32 * CK_STR];      // ck [p][rn] pad 40
    __shared__ uint32_t sSh[2][32 * SH_STR];   // per-warp S half [p][c'] pad 40

    const int tid  = threadIdx.x;
    const int warp = tid >> 5;      // c-half
    const int lane = tid & 31;
    const int bv   = blockIdx.x;
    const int g    = lane >> 2;
    const int tig  = lane & 3;

    if (blockIdx.x < 1024)
        g_W[blockIdx.x * 64 + tid] = __float2half_rn(W[blockIdx.x * 64 + tid]);

    // lane p = lane: gathered signal row base (in floats)
    const int2 ip = ((const int2*)pidx)[bv * P_ + lane];
    const int base = (ip.x * V_ + ip.y) * CIN;

    // Stage ck [p][rn]: 256 float4, both warps, coalesced
    {
        const float4* ck4 = (const float4*)(convk + (size_t)bv * 1024);
        #pragma unroll
        for (int j = 0; j < 4; ++j) {
            int f = j * 64 + tid;
            float4 v = ck4[f];
            int p = f >> 3, q = f & 7;
            uint4 u;
            u.x = f2tf32(v.x); u.y = f2tf32(v.y); u.z = f2tf32(v.z); u.w = f2tf32(v.w);
            *(uint4*)&sCK[p * CK_STR + q * 4] = u;
        }
    }
    // Stage own S half [p][c' 0..31] (global c = warp*32 + c')
    {
        uint32_t* sS = sSh[warp];
        #pragma unroll
        for (int j = 0; j < 8; ++j) {
            int f = j * 32 + lane;
            int p = f >> 3, q = f & 7;
            int bp = __shfl_sync(0xffffffffu, base, p);
            float4 v = *(const float4*)(signal + bp + warp * 32 + q * 4);
            uint4 u;
            u.x = f2tf32(v.x); u.y = f2tf32(v.y); u.z = f2tf32(v.z); u.w = f2tf32(v.w);
            *(uint4*)&sS[p * SH_STR + q * 4] = u;
        }
    }
    __syncthreads();

    // Warp: D[m=rn 32][n = its 32 c']: 2 mt x 4 nt x 4 ks
    const uint32_t* sS = sSh[warp];
    float acc[2][4][4];
    #pragma unroll
    for (int i = 0; i < 2; ++i)
        #pragma unroll
        for (int j = 0; j < 4; ++j)
            #pragma unroll
            for (int e = 0; e < 4; ++e) acc[i][j][e] = 0.0f;

    #pragma unroll
    for (int ks = 0; ks < 4; ++ks) {
        const int k0 = ks * 8;
        uint32_t a[2][4];
        #pragma unroll
        for (int mt = 0; mt < 2; ++mt) {
            a[mt][0] = sCK[(k0 + tig)     * CK_STR + mt * 16 + g];
            a[mt][1] = sCK[(k0 + tig)     * CK_STR + mt * 16 + g + 8];
            a[mt][2] = sCK[(k0 + tig + 4) * CK_STR + mt * 16 + g];
            a[mt][3] = sCK[(k0 + tig + 4) * CK_STR + mt * 16 + g + 8];
        }
        #pragma unroll
        for (int nt = 0; nt < 4; ++nt) {
            uint32_t b0 = sS[(k0 + tig)     * SH_STR + nt * 8 + g];
            uint32_t b1 = sS[(k0 + tig + 4) * SH_STR + nt * 8 + g];
            mma_tf32(acc[0][nt][0], acc[0][nt][1], acc[0][nt][2], acc[0][nt][3],
                     a[0][0], a[0][1], a[0][2], a[0][3], b0, b1);
            mma_tf32(acc[1][nt][0], acc[1][nt][1], acc[1][nt][2], acc[1][nt][3],
                     a[1][0], a[1][1], a[1][2], a[1][3], b0, b1);
        }
    }
    __syncwarp();

    // acc -> sY[c'][rn] (stride 36), own-warp overlay region
    uint32_t* sY = sSh[warp];   // [32][36] = 1152 words <= 1280
    #pragma unroll
    for (int mt = 0; mt < 2; ++mt) {
        #pragma unroll
        for (int nt = 0; nt < 4; ++nt) {
            const int c  = nt * 8 + 2 * tig;
            const int r0 = mt * 16 + g;
            sY[(c)     * SY_STR + r0]     = __float_as_uint(acc[mt][nt][0]);
            sY[(c + 1) * SY_STR + r0]     = __float_as_uint(acc[mt][nt][1]);
            sY[(c)     * SY_STR + r0 + 8] = __float_as_uint(acc[mt][nt][2]);
            sY[(c + 1) * SY_STR + r0 + 8] = __float_as_uint(acc[mt][nt][3]);
        }
    }
    __syncwarp();

    // Epilogue: lane owns c' = lane; read its 32-value column (both r),
    // 8 conflict-free LDS.128; l-sums; sqrt; pack 8 fp16; one uint4 store.
    {
        const uint32_t* col = sY + lane * SY_STR;
        float v[32];
        #pragma unroll
        for (int j = 0; j < 8; ++j) {
            uint4 q = *(const uint4*)&col[j * 4];
            v[j * 4 + 0] = __uint_as_float(q.x);
            v[j * 4 + 1] = __uint_as_float(q.y);
            v[j * 4 + 2] = __uint_as_float(q.z);
            v[j * 4 + 3] = __uint_as_float(q.w);
        }
        float s[8];
        #pragma unroll
        for (int r = 0; r < 2; ++r) {
            const float* w = v + r * 16;
            s[r * 4 + 0] = w[0] * w[0];
            s[r * 4 + 1] = w[1] * w[1] + w[2] * w[2] + w[3] * w[3];
            s[r * 4 + 2] = w[4] * w[4] + w[5] * w[5] + w[6] * w[6]
                         + w[7] * w[7] + w[8] * w[8];
            s[r * 4 + 3] = w[9] * w[9] + w[10] * w[10] + w[11] * w[11]
                         + w[12] * w[12] + w[13] * w[13] + w[14] * w[14]
                         + w[15] * w[15];
        }
        __half2 h0 = __floats2half2_rn(sqclip(s[0]), sqclip(s[1]));
        __half2 h1 = __floats2half2_rn(sqclip(s[2]), sqclip(s[3]));
        __half2 h2 = __floats2half2_rn(sqclip(s[4]), sqclip(s[5]));
        __half2 h3 = __floats2half2_rn(sqclip(s[6]), sqclip(s[7]));
        uint4 o;
        o.x = *(uint32_t*)&h0; o.y = *(uint32_t*)&h1;
        o.z = *(uint32_t*)&h2; o.w = *(uint32_t*)&h3;
        ((uint4*)g_ypow)[(size_t)bv * 64 + warp * 32 + lane] = o;
    }
}

// ---------------------------------------------------------------------------
// Kernel 2: out = ypow * W^T + bias, relu.  fp16 m16n8k16 mma.  CTA 128 thr,
// tile 64m x 128n, KT=32 halves (16-word rows, same XOR swizzle), 4-stage
// cp.async pipeline, ldmatrix.x4 frags.  Warp = 32m x 64n.
// ---------------------------------------------------------------------------
#define KT     32               // halves per k-tile
#define NKT    (K2 / KT)        // 16
#define M_BLK  64
#define N_BLK  128

// word offset of (row, 16B-chunk c) in a tile with 16-word rows
__device__ __forceinline__ int swz(int row, int c) {
    return row * 16 + ((c ^ ((row >> 1) & 3)) << 2);
}

__global__ __launch_bounds__(128, 4)
void out_gemm_kernel(const float* __restrict__ bias,
                     float* __restrict__ out)
{
    __shared__ uint32_t sA[4][M_BLK * 16];   // 4 x 4KB
    __shared__ uint32_t sB[4][N_BLK * 16];   // 4 x 8KB

    const int tid  = threadIdx.x;
    const int warp = tid >> 5;
    const int lane = tid & 31;
    const int g    = lane >> 2;
    const int tig  = lane & 3;
    const int wm   = warp >> 1;
    const int wn   = warp & 1;
    const int m0   = blockIdx.x * M_BLK;
    const int lrow = lane & 15;     // ldsm row-within-16
    const int lch  = lane >> 4;     // ldsm chunk select

    const __half* yp = g_ypow;

    float acc[2][8][4];
    #pragma unroll
    for (int a = 0; a < 2; ++a)
        #pragma unroll
        for (int b = 0; b < 8; ++b)
            #pragma unroll
            for (int c = 0; c < 4; ++c) acc[a][b][c] = 0.0f;

    auto stage = [&](int kt, int st) {
        #pragma unroll
        for (int i = 0; i < 2; ++i) {          // A: 256 chunks
            int id = tid + i * 128;
            int row = id >> 2, c = id & 3;
            cp_async16(smem_u32(&sA[st][swz(row, c)]),
                       yp + (size_t)(m0 + row) * K2 + kt * KT + c * 8);
        }
        #pragma unroll
        for (int i = 0; i < 4; ++i) {          // B: 512 chunks
            int id = tid + i * 128;
            int row = id >> 2, c = id & 3;
            cp_async16(smem_u32(&sB[st][swz(row, c)]),
                       g_W + (size_t)row * K2 + kt * KT + c * 8);
        }
        asm volatile("cp.async.commit_group;");
    };

    stage(0, 0);
    stage(1, 1);
    stage(2, 2);

    for (int kt = 0; kt < NKT; ++kt) {
        asm volatile("cp.async.wait_group 2;");
        __syncthreads();
        if (kt + 3 < NKT) stage(kt + 3, (kt + 3) & 3);
        else asm volatile("cp.async.commit_group;");
        const int st = kt & 3;

        #pragma unroll
        for (int ks = 0; ks < 2; ++ks) {       // two k16 steps per KT=32
            const int ch = ks * 2 + lch;
            uint32_t a[2][4];
            #pragma unroll
            for (int mi = 0; mi < 2; ++mi) {
                int row = wm * 32 + mi * 16 + lrow;
                ldsm_x4(a[mi], smem_u32(&sA[st][swz(row, ch)]));
            }
            uint32_t b[4][4];
            #pragma unroll
            for (int p = 0; p < 4; ++p) {
                int row = wn * 64 + p * 16 + lrow;
                ldsm_x4(b[p], smem_u32(&sB[st][swz(row, ch)]));
            }
            #pragma unroll
            for (int p = 0; p < 4; ++p) {
                // b[p]: r0=b0(even n-tile), r1=b0(odd), r2=b1(even), r3=b1(odd)
                mma_f16(acc[0][2*p][0], acc[0][2*p][1], acc[0][2*p][2], acc[0][2*p][3],
                        a[0][0], a[0][1], a[0][2], a[0][3], b[p][0], b[p][2]);
                mma_f16(acc[0][2*p+1][0], acc[0][2*p+1][1], acc[0][2*p+1][2], acc[0][2*p+1][3],
                        a[0][0], a[0][1], a[0][2], a[0][3], b[p][1], b[p][3]);
                mma_f16(acc[1][2*p][0], acc[1][2*p][1], acc[1][2*p][2], acc[1][2*p][3],
                        a[1][0], a[1][1], a[1][2], a[1][3], b[p][0], b[p][2]);
                mma_f16(acc[1][2*p+1][0], acc[1][2*p+1][1], acc[1][2*p+1][2], acc[1][2*p+1][3],
                        a[1][0], a[1][1], a[1][2], a[1][3], b[p][1], b[p][3]);
            }
        }
    }

    // Epilogue: bias + relu, float2 stores
    #pragma unroll
    for (int nt = 0; nt < 8; ++nt) {
        const int col = wn * 64 + nt * 8 + 2 * tig;
        const float b0 = __ldg(&bias[col]);
        const float b1 = __ldg(&bias[col + 1]);
        #pragma unroll
        for (int mi = 0; mi < 2; ++mi) {
            const int row = m0 + wm * 32 + mi * 16 + g;
            float2 v0, v1;
            v0.x = fmaxf(acc[mi][nt][0] + b0, 0.0f);
            v0.y = fmaxf(acc[mi][nt][1] + b1, 0.0f);
            v1.x = fmaxf(acc[mi][nt][2] + b0, 0.0f);
            v1.y = fmaxf(acc[mi][nt][3] + b1, 0.0f);
            *(float2*)(out + (size_t)row * COUT + col)       = v0;
            *(float2*)(out + (size_t)(row + 8) * COUT + col) = v1;
        }
    }
}

extern "C" void kernel_launch(void* const* d_in, const int* in_sizes, int n_in,
                              void* d_out, int out_size)
{
    const float* signal = (const float*)d_in[0];
    const int*   pidx   = (const int*)  d_in[1];
    const float* convk  = (const float*)d_in[2];
    const float* W      = (const float*)d_in[3];
    const float* bias   = (const float*)d_in[4];
    float* out = (float*)d_out;

    ypow_kernel<<<BV, 64>>>(signal, pidx, convk, W);
    out_gemm_kernel<<<BV / M_BLK, 128>>>(bias, out);
}

// round 9
// speedup vs baseline: 1.3617x; 1.1315x over previous
#include <cuda_runtime.h>
#include <cuda_fp16.h>
#include <cstdint>

#define B_    8
#define V_    4096
#define P_    32
#define CIN   64
#define COUT  128
#define BV    (B_ * V_)      // 32768
#define K2    512

// ypow [BV][K2] scratch in fp16, k = c*8 + r*4 + l (matches W flattening).
__device__ __half g_ypow[(size_t)BV * K2];
// W pre-converted to fp16 (filled by first 1024 CTAs of ypow_kernel)
__device__ __half g_W[(size_t)COUT * K2];

__device__ __forceinline__ void mma_f16(float& d0, float& d1, float& d2, float& d3,
                                        uint32_t a0, uint32_t a1, uint32_t a2, uint32_t a3,
                                        uint32_t b0, uint32_t b1) {
    asm volatile(
        "mma.sync.aligned.m16n8k16.row.col.f32.f16.f16.f32 "
        "{%0,%1,%2,%3}, {%4,%5,%6,%7}, {%8,%9}, {%0,%1,%2,%3};"
        : "+f"(d0), "+f"(d1), "+f"(d2), "+f"(d3)
        : "r"(a0), "r"(a1), "r"(a2), "r"(a3), "r"(b0), "r"(b1));
}

__device__ __forceinline__ void ldsm_x4(uint32_t* r, uint32_t addr) {
    asm volatile("ldmatrix.sync.aligned.m8n8.x4.shared.b16 {%0,%1,%2,%3}, [%4];"
        : "=r"(r[0]), "=r"(r[1]), "=r"(r[2]), "=r"(r[3]) : "r"(addr));
}

__device__ __forceinline__ void ldsm_x4_t(uint32_t* r, uint32_t addr) {
    asm volatile("ldmatrix.sync.aligned.m8n8.x4.trans.shared.b16 {%0,%1,%2,%3}, [%4];"
        : "=r"(r[0]), "=r"(r[1]), "=r"(r[2]), "=r"(r[3]) : "r"(addr));
}

__device__ __forceinline__ float sqclip(float x) {
    return sqrtf(fmaxf(x, 1e-4f));
}

__device__ __forceinline__ uint32_t smem_u32(const void* p) {
    return (uint32_t)__cvta_generic_to_shared(p);
}

__device__ __forceinline__ void cp_async16(uint32_t dst, const void* src) {
    asm volatile("cp.async.cg.shared.global [%0], [%1], 16;" :: "r"(dst), "l"(src));
}

// XOR swizzle for tiles with 16-word (64B) rows: chunk c in 0..3
__device__ __forceinline__ int swz(int row, int c) {
    return row * 16 + ((c ^ ((row >> 1) & 3)) << 2);
}

// pack 8 floats (two float4) -> 4 half2 words
__device__ __forceinline__ uint4 pack8h(float4 v0, float4 v1) {
    __half2 h0 = __floats2half2_rn(v0.x, v0.y);
    __half2 h1 = __floats2half2_rn(v0.z, v0.w);
    __half2 h2 = __floats2half2_rn(v1.x, v1.y);
    __half2 h3 = __floats2half2_rn(v1.z, v1.w);
    uint4 u;
    u.x = *(uint32_t*)&h0; u.y = *(uint32_t*)&h1;
    u.z = *(uint32_t*)&h2; u.w = *(uint32_t*)&h3;
    return u;
}

// ---------------------------------------------------------------------------
// Kernel 1: CTA = 64 threads = 2 warps = ONE bv, full fp16 datapath.
// D[m=rn 32][n=c'] = ck^T * S, fp16 m16n8k16 mma; warp h owns c-half h.
// ck & S staged as fp16 in XOR-swizzled tiles (STS.128, conflict-free);
// fragments via ldmatrix.x4.trans. Epilogue: fp16 bounce [c'][rn] pad-40,
// row LDS.128 reads, l-sums in fp32, sqrt, coalesced uint4 store.
// First 1024 CTAs convert W -> fp16.
// ---------------------------------------------------------------------------
#define YW_STR 40   // epilogue bounce row stride in halves (20 words)

__global__ __launch_bounds__(64, 14)
void ypow_kernel(const float* __restrict__ signal,
                 const int*   __restrict__ pidx,
                 const float* __restrict__ convk,
                 const float* __restrict__ W)
{
    __shared__ uint32_t sCK[32 * 16];     // fp16 [p][rn 32h] swizzled, 2KB
    __shared__ uint32_t sSh[2][640];      // per-warp: S tile (512w) / bounce (640w)

    const int tid  = threadIdx.x;
    const int warp = tid >> 5;      // c-half
    const int lane = tid & 31;
    const int bv   = blockIdx.x;
    const int g    = lane >> 2;
    const int tig  = lane & 3;
    const int grp  = lane >> 3;     // ldsm address group
    const int gi   = lane & 7;

    if (blockIdx.x < 1024)
        g_W[blockIdx.x * 64 + tid] = __float2half_rn(W[blockIdx.x * 64 + tid]);

    // lane p = lane: gathered signal row base (in floats)
    const int2 ip = ((const int2*)pidx)[bv * P_ + lane];
    const int base = (ip.x * V_ + ip.y) * CIN;

    // Stage ck [p][rn] -> fp16 swizzled: 128 chunks, 2 per thread
    {
        const float* ck = convk + (size_t)bv * 1024;
        #pragma unroll
        for (int it = 0; it < 2; ++it) {
            int id = tid + it * 64;
            int row = id >> 2, c = id & 3;
            const float4* src = (const float4*)(ck + row * 32 + c * 8);
            *(uint4*)&sCK[swz(row, c)] = pack8h(src[0], src[1]);
        }
    }
    // Stage own S half [p][c' 0..31] -> fp16 swizzled: 128 chunks, 4 per lane
    {
        uint32_t* sS = sSh[warp];
        #pragma unroll
        for (int j = 0; j < 4; ++j) {
            int id = j * 32 + lane;
            int row = id >> 2, c = id & 3;
            int bp = __shfl_sync(0xffffffffu, base, row);
            const float4* src = (const float4*)(signal + bp + warp * 32 + c * 8);
            *(uint4*)&sS[swz(row, c)] = pack8h(src[0], src[1]);
        }
    }
    __syncthreads();   // sCK written by both warps

    const uint32_t sCKb = smem_u32(sCK);
    const uint32_t sSb  = smem_u32(sSh[warp]);

    // D[m=rn 32][n = its 32 c']: 2 mt x 4 nt x 2 ks (k16 each)
    float acc[2][4][4];
    #pragma unroll
    for (int i = 0; i < 2; ++i)
        #pragma unroll
        for (int j = 0; j < 4; ++j)
            #pragma unroll
            for (int e = 0; e < 4; ++e) acc[i][j][e] = 0.0f;

    #pragma unroll
    for (int ks = 0; ks < 2; ++ks) {
        // A-frags from sCK ([k=p][m=rn]), trans.
        // groups: 0:(k+0,m+0) 1:(k+0,m+8) 2:(k+8,m+0) 3:(k+8,m+8)
        uint32_t a[2][4];
        #pragma unroll
        for (int mt = 0; mt < 2; ++mt) {
            int row = ks * 16 + (grp >> 1) * 8 + gi;
            int ch  = mt * 2 + (grp & 1);
            ldsm_x4_t(a[mt], sCKb + 4 * swz(row, ch));
        }
        // B-frags from sS ([k=p][n=c']), trans.
        // groups: 0:(k+0,n+0) 1:(k+8,n+0) 2:(k+0,n+8) 3:(k+8,n+8)
        // -> regs r0=b0(even nt), r1=b1(even), r2=b0(odd), r3=b1(odd)
        uint32_t b[2][4];
        #pragma unroll
        for (int ntp = 0; ntp < 2; ++ntp) {
            int row = ks * 16 + (grp & 1) * 8 + gi;
            int ch  = ntp * 2 + (grp >> 1);
            ldsm_x4_t(b[ntp], sSb + 4 * swz(row, ch));
        }
        #pragma unroll
        for (int mt = 0; mt < 2; ++mt)
            #pragma unroll
            for (int nt = 0; nt < 4; ++nt) {
                uint32_t b0 = b[nt >> 1][(nt & 1) * 2];
                uint32_t b1 = b[nt >> 1][(nt & 1) * 2 + 1];
                mma_f16(acc[mt][nt][0], acc[mt][nt][1], acc[mt][nt][2], acc[mt][nt][3],
                        a[mt][0], a[mt][1], a[mt][2], a[mt][3], b0, b1);
            }
    }
    __syncwarp();   // done reading own sS half; overlay it with fp16 bounce

    // acc -> bounce [c'][rn] fp16, rows padded to 40 halves.
    // d0,d1 = (rn = mt*16+g, c' = nt*8+2tig +{0,1}); d2,d3 = rn+8.
    __half* sY = (__half*)sSh[warp];
    #pragma unroll
    for (int mt = 0; mt < 2; ++mt) {
        #pragma unroll
        for (int nt = 0; nt < 4; ++nt) {
            const int c0 = nt * 8 + 2 * tig;
            const int rn = mt * 16 + g;
            sY[(c0)     * YW_STR + rn]     = __float2half_rn(acc[mt][nt][0]);
            sY[(c0 + 1) * YW_STR + rn]     = __float2half_rn(acc[mt][nt][1]);
            sY[(c0)     * YW_STR + rn + 8] = __float2half_rn(acc[mt][nt][2]);
            sY[(c0 + 1) * YW_STR + rn + 8] = __float2half_rn(acc[mt][nt][3]);
        }
    }
    __syncwarp();

    // Epilogue: lane owns c' = lane; read its 32 halves (4 aligned LDS.128,
    // 20-word row stride -> conflict-free); l-sums in fp32; sqrt; pack fp16.
    {
        const uint32_t* rowp = (const uint32_t*)(sY + lane * YW_STR);
        float v[32];
        #pragma unroll
        for (int j = 0; j < 4; ++j) {
            uint4 q = *(const uint4*)&rowp[j * 4];
            uint32_t w[4] = {q.x, q.y, q.z, q.w};
            #pragma unroll
            for (int e = 0; e < 4; ++e) {
                float2 f = __half22float2(*(const __half2*)&w[e]);
                v[j * 8 + e * 2]     = f.x;
                v[j * 8 + e * 2 + 1] = f.y;
            }
        }
        float s[8];
        #pragma unroll
        for (int r = 0; r < 2; ++r) {
            const float* w = v + r * 16;
            s[r * 4 + 0] = w[0] * w[0];
            s[r * 4 + 1] = w[1] * w[1] + w[2] * w[2] + w[3] * w[3];
            s[r * 4 + 2] = w[4] * w[4] + w[5] * w[5] + w[6] * w[6]
                         + w[7] * w[7] + w[8] * w[8];
            s[r * 4 + 3] = w[9] * w[9] + w[10] * w[10] + w[11] * w[11]
                         + w[12] * w[12] + w[13] * w[13] + w[14] * w[14]
                         + w[15] * w[15];
        }
        __half2 h0 = __floats2half2_rn(sqclip(s[0]), sqclip(s[1]));
        __half2 h1 = __floats2half2_rn(sqclip(s[2]), sqclip(s[3]));
        __half2 h2 = __floats2half2_rn(sqclip(s[4]), sqclip(s[5]));
        __half2 h3 = __floats2half2_rn(sqclip(s[6]), sqclip(s[7]));
        uint4 o;
        o.x = *(uint32_t*)&h0; o.y = *(uint32_t*)&h1;
        o.z = *(uint32_t*)&h2; o.w = *(uint32_t*)&h3;
        ((uint4*)g_ypow)[(size_t)bv * 64 + warp * 32 + lane] = o;
    }
}

// ---------------------------------------------------------------------------
// Kernel 2: out = ypow * W^T + bias, relu.  fp16 m16n8k16 mma.  CTA 128 thr,
// tile 64m x 128n, KT=32 halves, 4-stage cp.async pipeline, XOR swizzle,
// ldmatrix.x4 frags.  Warp = 32m x 64n.  (unchanged from R8)
// ---------------------------------------------------------------------------
#define KT     32
#define NKT    (K2 / KT)        // 16
#define M_BLK  64
#define N_BLK  128

__global__ __launch_bounds__(128, 4)
void out_gemm_kernel(const float* __restrict__ bias,
                     float* __restrict__ out)
{
    __shared__ uint32_t sA[4][M_BLK * 16];
    __shared__ uint32_t sB[4][N_BLK * 16];

    const int tid  = threadIdx.x;
    const int warp = tid >> 5;
    const int lane = tid & 31;
    const int g    = lane >> 2;
    const int tig  = lane & 3;
    const int wm   = warp >> 1;
    const int wn   = warp & 1;
    const int m0   = blockIdx.x * M_BLK;
    const int lrow = lane & 15;
    const int lch  = lane >> 4;

    const __half* yp = g_ypow;

    float acc[2][8][4];
    #pragma unroll
    for (int a = 0; a < 2; ++a)
        #pragma unroll
        for (int b = 0; b < 8; ++b)
            #pragma unroll
            for (int c = 0; c < 4; ++c) acc[a][b][c] = 0.0f;

    auto stage = [&](int kt, int st) {
        #pragma unroll
        for (int i = 0; i < 2; ++i) {
            int id = tid + i * 128;
            int row = id >> 2, c = id & 3;
            cp_async16(smem_u32(&sA[st][swz(row, c)]),
                       yp + (size_t)(m0 + row) * K2 + kt * KT + c * 8);
        }
        #pragma unroll
        for (int i = 0; i < 4; ++i) {
            int id = tid + i * 128;
            int row = id >> 2, c = id & 3;
            cp_async16(smem_u32(&sB[st][swz(row, c)]),
                       g_W + (size_t)row * K2 + kt * KT + c * 8);
        }
        asm volatile("cp.async.commit_group;");
    };

    stage(0, 0);
    stage(1, 1);
    stage(2, 2);

    for (int kt = 0; kt < NKT; ++kt) {
        asm volatile("cp.async.wait_group 2;");
        __syncthreads();
        if (kt + 3 < NKT) stage(kt + 3, (kt + 3) & 3);
        else asm volatile("cp.async.commit_group;");
        const int st = kt & 3;

        #pragma unroll
        for (int ks = 0; ks < 2; ++ks) {
            const int ch = ks * 2 + lch;
            uint32_t a[2][4];
            #pragma unroll
            for (int mi = 0; mi < 2; ++mi) {
                int row = wm * 32 + mi * 16 + lrow;
                ldsm_x4(a[mi], smem_u32(&sA[st][swz(row, ch)]));
            }
            uint32_t b[4][4];
            #pragma unroll
            for (int p = 0; p < 4; ++p) {
                int row = wn * 64 + p * 16 + lrow;
                ldsm_x4(b[p], smem_u32(&sB[st][swz(row, ch)]));
            }
            #pragma unroll
            for (int p = 0; p < 4; ++p) {
                mma_f16(acc[0][2*p][0], acc[0][2*p][1], acc[0][2*p][2], acc[0][2*p][3],
                        a[0][0], a[0][1], a[0][2], a[0][3], b[p][0], b[p][2]);
                mma_f16(acc[0][2*p+1][0], acc[0][2*p+1][1], acc[0][2*p+1][2], acc[0][2*p+1][3],
                        a[0][0], a[0][1], a[0][2], a[0][3], b[p][1], b[p][3]);
                mma_f16(acc[1][2*p][0], acc[1][2*p][1], acc[1][2*p][2], acc[1][2*p][3],
                        a[1][0], a[1][1], a[1][2], a[1][3], b[p][0], b[p][2]);
                mma_f16(acc[1][2*p+1][0], acc[1][2*p+1][1], acc[1][2*p+1][2], acc[1][2*p+1][3],
                        a[1][0], a[1][1], a[1][2], a[1][3], b[p][1], b[p][3]);
            }
        }
    }

    #pragma unroll
    for (int nt = 0; nt < 8; ++nt) {
        const int col = wn * 64 + nt * 8 + 2 * tig;
        const float b0 = __ldg(&bias[col]);
        const float b1 = __ldg(&bias[col + 1]);
        #pragma unroll
        for (int mi = 0; mi < 2; ++mi) {
            const int row = m0 + wm * 32 + mi * 16 + g;
            float2 v0, v1;
            v0.x = fmaxf(acc[mi][nt][0] + b0, 0.0f);
            v0.y = fmaxf(acc[mi][nt][1] + b1, 0.0f);
            v1.x = fmaxf(acc[mi][nt][2] + b0, 0.0f);
            v1.y = fmaxf(acc[mi][nt][3] + b1, 0.0f);
            *(float2*)(out + (size_t)row * COUT + col)       = v0;
            *(float2*)(out + (size_t)(row + 8) * COUT + col) = v1;
        }
    }
}

extern "C" void kernel_launch(void* const* d_in, const int* in_sizes, int n_in,
                              void* d_out, int out_size)
{
    const float* signal = (const float*)d_in[0];
    const int*   pidx   = (const int*)  d_in[1];
    const float* convk  = (const float*)d_in[2];
    const float* W      = (const float*)d_in[3];
    const float* bias   = (const float*)d_in[4];
    float* out = (float*)d_out;

    ypow_kernel<<<BV, 64>>>(signal, pidx, convk, W);
    out_gemm_kernel<<<BV / M_BLK, 128>>>(bias, out);
}

// round 10
// speedup vs baseline: 1.3623x; 1.0004x over previous
#include <cuda_runtime.h>
#include <cuda_fp16.h>
#include <cstdint>

#define B_    8
#define V_    4096
#define P_    32
#define CIN   64
#define COUT  128
#define BV    (B_ * V_)      // 32768
#define K2    512

// ypow [BV][K2] scratch in fp16, k = c*8 + r*4 + l (matches W flattening).
__device__ __half g_ypow[(size_t)BV * K2];
// W pre-converted to fp16 (filled by first 1024 CTAs of ypow_kernel)
__device__ __half g_W[(size_t)COUT * K2];

__device__ __forceinline__ void mma_f16(float& d0, float& d1, float& d2, float& d3,
                                        uint32_t a0, uint32_t a1, uint32_t a2, uint32_t a3,
                                        uint32_t b0, uint32_t b1) {
    asm volatile(
        "mma.sync.aligned.m16n8k16.row.col.f32.f16.f16.f32 "
        "{%0,%1,%2,%3}, {%4,%5,%6,%7}, {%8,%9}, {%0,%1,%2,%3};"
        : "+f"(d0), "+f"(d1), "+f"(d2), "+f"(d3)
        : "r"(a0), "r"(a1), "r"(a2), "r"(a3), "r"(b0), "r"(b1));
}

__device__ __forceinline__ void ldsm_x4(uint32_t* r, uint32_t addr) {
    asm volatile("ldmatrix.sync.aligned.m8n8.x4.shared.b16 {%0,%1,%2,%3}, [%4];"
        : "=r"(r[0]), "=r"(r[1]), "=r"(r[2]), "=r"(r[3]) : "r"(addr));
}

__device__ __forceinline__ void ldsm_x4_t(uint32_t* r, uint32_t addr) {
    asm volatile("ldmatrix.sync.aligned.m8n8.x4.trans.shared.b16 {%0,%1,%2,%3}, [%4];"
        : "=r"(r[0]), "=r"(r[1]), "=r"(r[2]), "=r"(r[3]) : "r"(addr));
}

__device__ __forceinline__ float sqclip(float x) {
    return sqrtf(fmaxf(x, 1e-4f));
}

__device__ __forceinline__ uint32_t smem_u32(const void* p) {
    return (uint32_t)__cvta_generic_to_shared(p);
}

__device__ __forceinline__ void cp_async16(uint32_t dst, const void* src) {
    asm volatile("cp.async.cg.shared.global [%0], [%1], 16;" :: "r"(dst), "l"(src));
}

// XOR swizzle for tiles with 16-word (64B) rows: chunk c in 0..3
__device__ __forceinline__ int swz(int row, int c) {
    return row * 16 + ((c ^ ((row >> 1) & 3)) << 2);
}

// pack 8 floats (two float4) -> 4 half2 words
__device__ __forceinline__ uint4 pack8h(float4 v0, float4 v1) {
    __half2 h0 = __floats2half2_rn(v0.x, v0.y);
    __half2 h1 = __floats2half2_rn(v0.z, v0.w);
    __half2 h2 = __floats2half2_rn(v1.x, v1.y);
    __half2 h3 = __floats2half2_rn(v1.z, v1.w);
    uint4 u;
    u.x = *(uint32_t*)&h0; u.y = *(uint32_t*)&h1;
    u.z = *(uint32_t*)&h2; u.w = *(uint32_t*)&h3;
    return u;
}

// ---------------------------------------------------------------------------
// Kernel 1: CTA = 64 threads = 2 warps = ONE bv, full fp16 datapath.
// D[m=rn 32][n=c'] = ck^T * S, fp16 m16n8k16 mma; warp h owns c-half h.
// Bounce layout: [c2 = c'/2][rn] of half2 (both c's of the pair packed),
// row stride 36 words -- STS.32 and LDS.128 both conflict-free.
// Epilogue: lane = (c2, r-half); 4x LDS.128; l-sums; r-half exchange via
// 4 shfl.xor(16); one fully-coalesced uint4 STG per lane.
// First 1024 CTAs convert W -> fp16.
// ---------------------------------------------------------------------------
#define YB_STR 36   // bounce row stride in words (half2 units)

__global__ __launch_bounds__(64, 14)
void ypow_kernel(const float* __restrict__ signal,
                 const int*   __restrict__ pidx,
                 const float* __restrict__ convk,
                 const float* __restrict__ W)
{
    __shared__ uint32_t sCK[32 * 16];     // fp16 [p][rn 32h] swizzled, 2KB
    __shared__ uint32_t sSh[2][640];      // per-warp: S tile (512w) / bounce (576w)

    const int tid  = threadIdx.x;
    const int warp = tid >> 5;      // c-half
    const int lane = tid & 31;
    const int bv   = blockIdx.x;
    const int g    = lane >> 2;
    const int tig  = lane & 3;
    const int grp  = lane >> 3;     // ldsm address group
    const int gi   = lane & 7;

    if (blockIdx.x < 1024)
        g_W[blockIdx.x * 64 + tid] = __float2half_rn(W[blockIdx.x * 64 + tid]);

    // lane p = lane: gathered signal row base (in floats)
    const int2 ip = ((const int2*)pidx)[bv * P_ + lane];
    const int base = (ip.x * V_ + ip.y) * CIN;

    // Stage ck [p][rn] -> fp16 swizzled: 128 chunks, 2 per thread
    {
        const float* ck = convk + (size_t)bv * 1024;
        #pragma unroll
        for (int it = 0; it < 2; ++it) {
            int id = tid + it * 64;
            int row = id >> 2, c = id & 3;
            const float4* src = (const float4*)(ck + row * 32 + c * 8);
            *(uint4*)&sCK[swz(row, c)] = pack8h(src[0], src[1]);
        }
    }
    // Stage own S half [p][c' 0..31] -> fp16 swizzled: 128 chunks, 4 per lane
    {
        uint32_t* sS = sSh[warp];
        #pragma unroll
        for (int j = 0; j < 4; ++j) {
            int id = j * 32 + lane;
            int row = id >> 2, c = id & 3;
            int bp = __shfl_sync(0xffffffffu, base, row);
            const float4* src = (const float4*)(signal + bp + warp * 32 + c * 8);
            *(uint4*)&sS[swz(row, c)] = pack8h(src[0], src[1]);
        }
    }
    __syncthreads();   // sCK written by both warps

    const uint32_t sCKb = smem_u32(sCK);
    const uint32_t sSb  = smem_u32(sSh[warp]);

    // D[m=rn 32][n = its 32 c']: 2 mt x 4 nt x 2 ks (k16 each)
    float acc[2][4][4];
    #pragma unroll
    for (int i = 0; i < 2; ++i)
        #pragma unroll
        for (int j = 0; j < 4; ++j)
            #pragma unroll
            for (int e = 0; e < 4; ++e) acc[i][j][e] = 0.0f;

    #pragma unroll
    for (int ks = 0; ks < 2; ++ks) {
        uint32_t a[2][4];
        #pragma unroll
        for (int mt = 0; mt < 2; ++mt) {
            int row = ks * 16 + (grp >> 1) * 8 + gi;
            int ch  = mt * 2 + (grp & 1);
            ldsm_x4_t(a[mt], sCKb + 4 * swz(row, ch));
        }
        uint32_t b[2][4];
        #pragma unroll
        for (int ntp = 0; ntp < 2; ++ntp) {
            int row = ks * 16 + (grp & 1) * 8 + gi;
            int ch  = ntp * 2 + (grp >> 1);
            ldsm_x4_t(b[ntp], sSb + 4 * swz(row, ch));
        }
        #pragma unroll
        for (int mt = 0; mt < 2; ++mt)
            #pragma unroll
            for (int nt = 0; nt < 4; ++nt) {
                uint32_t b0 = b[nt >> 1][(nt & 1) * 2];
                uint32_t b1 = b[nt >> 1][(nt & 1) * 2 + 1];
                mma_f16(acc[mt][nt][0], acc[mt][nt][1], acc[mt][nt][2], acc[mt][nt][3],
                        a[mt][0], a[mt][1], a[mt][2], a[mt][3], b0, b1);
            }
    }
    __syncwarp();   // done reading own sS half; overlay it with bounce

    // acc -> bounce [c2][rn] half2 (c-pair packed), 16 STS.32, conflict-free.
    uint32_t* sY = sSh[warp];
    #pragma unroll
    for (int mt = 0; mt < 2; ++mt) {
        #pragma unroll
        for (int nt = 0; nt < 4; ++nt) {
            const int c2 = nt * 4 + tig;
            const int rn = mt * 16 + g;
            __half2 h01 = __floats2half2_rn(acc[mt][nt][0], acc[mt][nt][1]);
            __half2 h23 = __floats2half2_rn(acc[mt][nt][2], acc[mt][nt][3]);
            sY[c2 * YB_STR + rn]     = *(uint32_t*)&h01;
            sY[c2 * YB_STR + rn + 8] = *(uint32_t*)&h23;
        }
    }
    __syncwarp();

    // Epilogue: lane = (c2 = lane&15, r = lane>>4).  4x LDS.128 reads its
    // 16 rn x 2 c halves; l-sums in fp32; sqrt; pack; exchange r-halves with
    // lane^16; coalesced uint4 store.
    {
        const uint32_t* rp = sY + (lane & 15) * YB_STR + (lane >> 4) * 16;
        float vc0[16], vc1[16];
        #pragma unroll
        for (int j = 0; j < 4; ++j) {
            uint4 q = *(const uint4*)&rp[j * 4];
            uint32_t w[4] = {q.x, q.y, q.z, q.w};
            #pragma unroll
            for (int e = 0; e < 4; ++e) {
                float2 f = __half22float2(*(const __half2*)&w[e]);
                vc0[j * 4 + e] = f.x;
                vc1[j * 4 + e] = f.y;
            }
        }
        float s0[4], s1[4];
        {
            s0[0] = vc0[0] * vc0[0];
            s0[1] = vc0[1] * vc0[1] + vc0[2] * vc0[2] + vc0[3] * vc0[3];
            s0[2] = vc0[4] * vc0[4] + vc0[5] * vc0[5] + vc0[6] * vc0[6]
                  + vc0[7] * vc0[7] + vc0[8] * vc0[8];
            s0[3] = vc0[9] * vc0[9] + vc0[10] * vc0[10] + vc0[11] * vc0[11]
                  + vc0[12] * vc0[12] + vc0[13] * vc0[13] + vc0[14] * vc0[14]
                  + vc0[15] * vc0[15];
            s1[0] = vc1[0] * vc1[0];
            s1[1] = vc1[1] * vc1[1] + vc1[2] * vc1[2] + vc1[3] * vc1[3];
            s1[2] = vc1[4] * vc1[4] + vc1[5] * vc1[5] + vc1[6] * vc1[6]
                  + vc1[7] * vc1[7] + vc1[8] * vc1[8];
            s1[3] = vc1[9] * vc1[9] + vc1[10] * vc1[10] + vc1[11] * vc1[11]
                  + vc1[12] * vc1[12] + vc1[13] * vc1[13] + vc1[14] * vc1[14]
                  + vc1[15] * vc1[15];
        }
        __half2 u0 = __floats2half2_rn(sqclip(s0[0]), sqclip(s0[1]));
        __half2 u1 = __floats2half2_rn(sqclip(s0[2]), sqclip(s0[3]));
        __half2 u2 = __floats2half2_rn(sqclip(s1[0]), sqclip(s1[1]));
        __half2 u3 = __floats2half2_rn(sqclip(s1[2]), sqclip(s1[3]));
        uint32_t w0 = *(uint32_t*)&u0, w1 = *(uint32_t*)&u1;
        uint32_t w2 = *(uint32_t*)&u2, w3 = *(uint32_t*)&u3;
        // exchange with partner lane (other r, same c2)
        uint32_t p0 = __shfl_xor_sync(0xffffffffu, w0, 16);
        uint32_t p1 = __shfl_xor_sync(0xffffffffu, w1, 16);
        uint32_t p2 = __shfl_xor_sync(0xffffffffu, w2, 16);
        uint32_t p3 = __shfl_xor_sync(0xffffffffu, w3, 16);
        uint4 o;
        int c;
        if (lane < 16) {          // keep column c = 2*c2: own = r0, partner = r1
            c = 2 * (lane & 15);
            o.x = w0; o.y = w1; o.z = p0; o.w = p1;
        } else {                  // keep column c = 2*c2+1: partner = r0, own = r1
            c = 2 * (lane & 15) + 1;
            o.x = p2; o.y = p3; o.z = w2; o.w = w3;
        }
        ((uint4*)g_ypow)[(size_t)bv * 64 + warp * 32 + c] = o;
    }
}

// ---------------------------------------------------------------------------
// Kernel 2: out = ypow * W^T + bias, relu.  fp16 m16n8k16 mma.  CTA 256 thr,
// tile 128m x 128n (halves W L2 traffic), KT=32 halves, 4-stage cp.async
// pipeline, XOR swizzle, ldmatrix.x4 frags.  Warp = 32m x 64n.
// ---------------------------------------------------------------------------
#define KT     32
#define NKT    (K2 / KT)        // 16
#define M_BLK  128
#define N_BLK  128

__global__ __launch_bounds__(256, 2)
void out_gemm_kernel(const float* __restrict__ bias,
                     float* __restrict__ out)
{
    __shared__ uint32_t sA[4][M_BLK * 16];   // 4 x 8KB
    __shared__ uint32_t sB[4][N_BLK * 16];   // 4 x 8KB

    const int tid  = threadIdx.x;
    const int warp = tid >> 5;
    const int lane = tid & 31;
    const int g    = lane >> 2;
    const int tig  = lane & 3;
    const int wm   = warp >> 1;        // 0..3
    const int wn   = warp & 1;         // 0..1
    const int m0   = blockIdx.x * M_BLK;
    const int lrow = lane & 15;
    const int lch  = lane >> 4;

    const __half* yp = g_ypow;

    float acc[2][8][4];
    #pragma unroll
    for (int a = 0; a < 2; ++a)
        #pragma unroll
        for (int b = 0; b < 8; ++b)
            #pragma unroll
            for (int c = 0; c < 4; ++c) acc[a][b][c] = 0.0f;

    auto stage = [&](int kt, int st) {
        #pragma unroll
        for (int i = 0; i < 2; ++i) {          // A: 512 chunks
            int id = tid + i * 256;
            int row = id >> 2, c = id & 3;
            cp_async16(smem_u32(&sA[st][swz(row, c)]),
                       yp + (size_t)(m0 + row) * K2 + kt * KT + c * 8);
        }
        #pragma unroll
        for (int i = 0; i < 2; ++i) {          // B: 512 chunks
            int id = tid + i * 256;
            int row = id >> 2, c = id & 3;
            cp_async16(smem_u32(&sB[st][swz(row, c)]),
                       g_W + (size_t)row * K2 + kt * KT + c * 8);
        }
        asm volatile("cp.async.commit_group;");
    };

    stage(0, 0);
    stage(1, 1);
    stage(2, 2);

    for (int kt = 0; kt < NKT; ++kt) {
        asm volatile("cp.async.wait_group 2;");
        __syncthreads();
        if (kt + 3 < NKT) stage(kt + 3, (kt + 3) & 3);
        else asm volatile("cp.async.commit_group;");
        const int st = kt & 3;

        #pragma unroll
        for (int ks = 0; ks < 2; ++ks) {
            const int ch = ks * 2 + lch;
            uint32_t a[2][4];
            #pragma unroll
            for (int mi = 0; mi < 2; ++mi) {
                int row = wm * 32 + mi * 16 + lrow;
                ldsm_x4(a[mi], smem_u32(&sA[st][swz(row, ch)]));
            }
            uint32_t b[4][4];
            #pragma unroll
            for (int p = 0; p < 4; ++p) {
                int row = wn * 64 + p * 16 + lrow;
                ldsm_x4(b[p], smem_u32(&sB[st][swz(row, ch)]));
            }
            #pragma unroll
            for (int p = 0; p < 4; ++p) {
                mma_f16(acc[0][2*p][0], acc[0][2*p][1], acc[0][2*p][2], acc[0][2*p][3],
                        a[0][0], a[0][1], a[0][2], a[0][3], b[p][0], b[p][2]);
                mma_f16(acc[0][2*p+1][0], acc[0][2*p+1][1], acc[0][2*p+1][2], acc[0][2*p+1][3],
                        a[0][0], a[0][1], a[0][2], a[0][3], b[p][1], b[p][3]);
                mma_f16(acc[1][2*p][0], acc[1][2*p][1], acc[1][2*p][2], acc[1][2*p][3],
                        a[1][0], a[1][1], a[1][2], a[1][3], b[p][0], b[p][2]);
                mma_f16(acc[1][2*p+1][0], acc[1][2*p+1][1], acc[1][2*p+1][2], acc[1][2*p+1][3],
                        a[1][0], a[1][1], a[1][2], a[1][3], b[p][1], b[p][3]);
            }
        }
    }

    #pragma unroll
    for (int nt = 0; nt < 8; ++nt) {
        const int col = wn * 64 + nt * 8 + 2 * tig;
        const float b0 = __ldg(&bias[col]);
        const float b1 = __ldg(&bias[col + 1]);
        #pragma unroll
        for (int mi = 0; mi < 2; ++mi) {
            const int row = m0 + wm * 32 + mi * 16 + g;
            float2 v0, v1;
            v0.x = fmaxf(acc[mi][nt][0] + b0, 0.0f);
            v0.y = fmaxf(acc[mi][nt][1] + b1, 0.0f);
            v1.x = fmaxf(acc[mi][nt][2] + b0, 0.0f);
            v1.y = fmaxf(acc[mi][nt][3] + b1, 0.0f);
            *(float2*)(out + (size_t)row * COUT + col)       = v0;
            *(float2*)(out + (size_t)(row + 8) * COUT + col) = v1;
        }
    }
}

extern "C" void kernel_launch(void* const* d_in, const int* in_sizes, int n_in,
                              void* d_out, int out_size)
{
    const float* signal = (const float*)d_in[0];
    const int*   pidx   = (const int*)  d_in[1];
    const float* convk  = (const float*)d_in[2];
    const float* W      = (const float*)d_in[3];
    const float* bias   = (const float*)d_in[4];
    float* out = (float*)d_out;

    ypow_kernel<<<BV, 64>>>(signal, pidx, convk, W);
    out_gemm_kernel<<<BV / M_BLK, 256>>>(bias, out);
}

// round 11
// speedup vs baseline: 1.4297x; 1.0495x over previous
#include <cuda_runtime.h>
#include <cuda_fp16.h>
#include <cstdint>

#define B_    8
#define V_    4096
#define P_    32
#define CIN   64
#define COUT  128
#define BV    (B_ * V_)      // 32768
#define K2    512

// ypow [BV][K2] scratch in fp16, k = c*8 + r*4 + l (matches W flattening).
__device__ __half g_ypow[(size_t)BV * K2];
// W pre-converted to fp16 (filled by first 1024 CTAs of ypow_kernel)
__device__ __half g_W[(size_t)COUT * K2];
// signal pre-converted to fp16 (prologue kernel) -- halves gather L2 traffic
__device__ __half g_S16[(size_t)B_ * V_ * CIN];

__device__ __forceinline__ void mma_f16(float& d0, float& d1, float& d2, float& d3,
                                        uint32_t a0, uint32_t a1, uint32_t a2, uint32_t a3,
                                        uint32_t b0, uint32_t b1) {
    asm volatile(
        "mma.sync.aligned.m16n8k16.row.col.f32.f16.f16.f32 "
        "{%0,%1,%2,%3}, {%4,%5,%6,%7}, {%8,%9}, {%0,%1,%2,%3};"
        : "+f"(d0), "+f"(d1), "+f"(d2), "+f"(d3)
        : "r"(a0), "r"(a1), "r"(a2), "r"(a3), "r"(b0), "r"(b1));
}

__device__ __forceinline__ void ldsm_x4(uint32_t* r, uint32_t addr) {
    asm volatile("ldmatrix.sync.aligned.m8n8.x4.shared.b16 {%0,%1,%2,%3}, [%4];"
        : "=r"(r[0]), "=r"(r[1]), "=r"(r[2]), "=r"(r[3]) : "r"(addr));
}

__device__ __forceinline__ void ldsm_x4_t(uint32_t* r, uint32_t addr) {
    asm volatile("ldmatrix.sync.aligned.m8n8.x4.trans.shared.b16 {%0,%1,%2,%3}, [%4];"
        : "=r"(r[0]), "=r"(r[1]), "=r"(r[2]), "=r"(r[3]) : "r"(addr));
}

__device__ __forceinline__ float sqclip(float x) {
    return sqrtf(fmaxf(x, 1e-4f));
}

__device__ __forceinline__ uint32_t smem_u32(const void* p) {
    return (uint32_t)__cvta_generic_to_shared(p);
}

__device__ __forceinline__ void cp_async16(uint32_t dst, const void* src) {
    asm volatile("cp.async.cg.shared.global [%0], [%1], 16;" :: "r"(dst), "l"(src));
}

// XOR swizzle for tiles with 16-word (64B) rows: chunk c in 0..3
__device__ __forceinline__ int swz(int row, int c) {
    return row * 16 + ((c ^ ((row >> 1) & 3)) << 2);
}

// pack 8 floats (two float4) -> 4 half2 words
__device__ __forceinline__ uint4 pack8h(float4 v0, float4 v1) {
    __half2 h0 = __floats2half2_rn(v0.x, v0.y);
    __half2 h1 = __floats2half2_rn(v0.z, v0.w);
    __half2 h2 = __floats2half2_rn(v1.x, v1.y);
    __half2 h3 = __floats2half2_rn(v1.z, v1.w);
    uint4 u;
    u.x = *(uint32_t*)&h0; u.y = *(uint32_t*)&h1;
    u.z = *(uint32_t*)&h2; u.w = *(uint32_t*)&h3;
    return u;
}

// ---------------------------------------------------------------------------
// Prologue: signal fp32 -> fp16 (2M elems; ~2us).  4 elems/thread.
// ---------------------------------------------------------------------------
__global__ __launch_bounds__(256)
void sig2h_kernel(const float* __restrict__ signal) {
    int i = blockIdx.x * 256 + threadIdx.x;         // float4 index
    float4 v = ((const float4*)signal)[i];
    __half2 h0 = __floats2half2_rn(v.x, v.y);
    __half2 h1 = __floats2half2_rn(v.z, v.w);
    uint2 u;
    u.x = *(uint32_t*)&h0; u.y = *(uint32_t*)&h1;
    ((uint2*)g_S16)[i] = u;
}

// ---------------------------------------------------------------------------
// Kernel 1: CTA = 64 threads = 2 warps = ONE bv, full fp16 datapath.
// D[m=rn 32][n=c'] = ck^T * S, fp16 m16n8k16 mma; warp h owns c-half h.
// S gathered directly from fp16 g_S16 (128B rows, raw uint4 copy).
// Bounce layout: [c2][rn] half2, stride 36 words.  Epilogue via r-half
// shuffle exchange, coalesced uint4 STG.  First 1024 CTAs convert W.
// ---------------------------------------------------------------------------
#define YB_STR 36   // bounce row stride in words (half2 units)

__global__ __launch_bounds__(64, 14)
void ypow_kernel(const __half* __restrict__ sig16_unused,
                 const int*   __restrict__ pidx,
                 const float* __restrict__ convk,
                 const float* __restrict__ W)
{
    __shared__ uint32_t sCK[32 * 16];     // fp16 [p][rn 32h] swizzled, 2KB
    __shared__ uint32_t sSh[2][640];      // per-warp: S tile (512w) / bounce (576w)

    const int tid  = threadIdx.x;
    const int warp = tid >> 5;      // c-half
    const int lane = tid & 31;
    const int bv   = blockIdx.x;
    const int g    = lane >> 2;
    const int tig  = lane & 3;
    const int grp  = lane >> 3;     // ldsm address group
    const int gi   = lane & 7;

    if (blockIdx.x < 1024)
        g_W[blockIdx.x * 64 + tid] = __float2half_rn(W[blockIdx.x * 64 + tid]);

    // lane p = lane: gathered signal row base (in halves)
    const int2 ip = ((const int2*)pidx)[bv * P_ + lane];
    const int base = (ip.x * V_ + ip.y) * CIN;

    // Stage ck [p][rn] -> fp16 swizzled: 128 chunks, 2 per thread
    {
        const float* ck = convk + (size_t)bv * 1024;
        #pragma unroll
        for (int it = 0; it < 2; ++it) {
            int id = tid + it * 64;
            int row = id >> 2, c = id & 3;
            const float4* src = (const float4*)(ck + row * 32 + c * 8);
            *(uint4*)&sCK[swz(row, c)] = pack8h(src[0], src[1]);
        }
    }
    // Stage own S half [p][c' 0..31] from fp16 source: raw uint4 copy
    {
        uint32_t* sS = sSh[warp];
        #pragma unroll
        for (int j = 0; j < 4; ++j) {
            int id = j * 32 + lane;
            int row = id >> 2, c = id & 3;
            int bp = __shfl_sync(0xffffffffu, base, row);
            uint4 v = *(const uint4*)(g_S16 + bp + warp * 32 + c * 8);
            *(uint4*)&sS[swz(row, c)] = v;
        }
    }
    __syncthreads();   // sCK written by both warps

    const uint32_t sCKb = smem_u32(sCK);
    const uint32_t sSb  = smem_u32(sSh[warp]);

    // D[m=rn 32][n = its 32 c']: 2 mt x 4 nt x 2 ks (k16 each)
    float acc[2][4][4];
    #pragma unroll
    for (int i = 0; i < 2; ++i)
        #pragma unroll
        for (int j = 0; j < 4; ++j)
            #pragma unroll
            for (int e = 0; e < 4; ++e) acc[i][j][e] = 0.0f;

    #pragma unroll
    for (int ks = 0; ks < 2; ++ks) {
        uint32_t a[2][4];
        #pragma unroll
        for (int mt = 0; mt < 2; ++mt) {
            int row = ks * 16 + (grp >> 1) * 8 + gi;
            int ch  = mt * 2 + (grp & 1);
            ldsm_x4_t(a[mt], sCKb + 4 * swz(row, ch));
        }
        uint32_t b[2][4];
        #pragma unroll
        for (int ntp = 0; ntp < 2; ++ntp) {
            int row = ks * 16 + (grp & 1) * 8 + gi;
            int ch  = ntp * 2 + (grp >> 1);
            ldsm_x4_t(b[ntp], sSb + 4 * swz(row, ch));
        }
        #pragma unroll
        for (int mt = 0; mt < 2; ++mt)
            #pragma unroll
            for (int nt = 0; nt < 4; ++nt) {
                uint32_t b0 = b[nt >> 1][(nt & 1) * 2];
                uint32_t b1 = b[nt >> 1][(nt & 1) * 2 + 1];
                mma_f16(acc[mt][nt][0], acc[mt][nt][1], acc[mt][nt][2], acc[mt][nt][3],
                        a[mt][0], a[mt][1], a[mt][2], a[mt][3], b0, b1);
            }
    }
    __syncwarp();   // done reading own sS half; overlay it with bounce

    // acc -> bounce [c2][rn] half2 (c-pair packed), 16 STS.32, conflict-free.
    uint32_t* sY = sSh[warp];
    #pragma unroll
    for (int mt = 0; mt < 2; ++mt) {
        #pragma unroll
        for (int nt = 0; nt < 4; ++nt) {
            const int c2 = nt * 4 + tig;
            const int rn = mt * 16 + g;
            __half2 h01 = __floats2half2_rn(acc[mt][nt][0], acc[mt][nt][1]);
            __half2 h23 = __floats2half2_rn(acc[mt][nt][2], acc[mt][nt][3]);
            sY[c2 * YB_STR + rn]     = *(uint32_t*)&h01;
            sY[c2 * YB_STR + rn + 8] = *(uint32_t*)&h23;
        }
    }
    __syncwarp();

    // Epilogue: lane = (c2 = lane&15, r = lane>>4).  4x LDS.128; l-sums in
    // fp32; sqrt; pack; r-half exchange via shfl.xor(16); coalesced uint4 STG.
    {
        const uint32_t* rp = sY + (lane & 15) * YB_STR + (lane >> 4) * 16;
        float vc0[16], vc1[16];
        #pragma unroll
        for (int j = 0; j < 4; ++j) {
            uint4 q = *(const uint4*)&rp[j * 4];
            uint32_t w[4] = {q.x, q.y, q.z, q.w};
            #pragma unroll
            for (int e = 0; e < 4; ++e) {
                float2 f = __half22float2(*(const __half2*)&w[e]);
                vc0[j * 4 + e] = f.x;
                vc1[j * 4 + e] = f.y;
            }
        }
        float s0[4], s1[4];
        s0[0] = vc0[0] * vc0[0];
        s0[1] = vc0[1] * vc0[1] + vc0[2] * vc0[2] + vc0[3] * vc0[3];
        s0[2] = vc0[4] * vc0[4] + vc0[5] * vc0[5] + vc0[6] * vc0[6]
              + vc0[7] * vc0[7] + vc0[8] * vc0[8];
        s0[3] = vc0[9] * vc0[9] + vc0[10] * vc0[10] + vc0[11] * vc0[11]
              + vc0[12] * vc0[12] + vc0[13] * vc0[13] + vc0[14] * vc0[14]
              + vc0[15] * vc0[15];
        s1[0] = vc1[0] * vc1[0];
        s1[1] = vc1[1] * vc1[1] + vc1[2] * vc1[2] + vc1[3] * vc1[3];
        s1[2] = vc1[4] * vc1[4] + vc1[5] * vc1[5] + vc1[6] * vc1[6]
              + vc1[7] * vc1[7] + vc1[8] * vc1[8];
        s1[3] = vc1[9] * vc1[9] + vc1[10] * vc1[10] + vc1[11] * vc1[11]
              + vc1[12] * vc1[12] + vc1[13] * vc1[13] + vc1[14] * vc1[14]
              + vc1[15] * vc1[15];
        __half2 u0 = __floats2half2_rn(sqclip(s0[0]), sqclip(s0[1]));
        __half2 u1 = __floats2half2_rn(sqclip(s0[2]), sqclip(s0[3]));
        __half2 u2 = __floats2half2_rn(sqclip(s1[0]), sqclip(s1[1]));
        __half2 u3 = __floats2half2_rn(sqclip(s1[2]), sqclip(s1[3]));
        uint32_t w0 = *(uint32_t*)&u0, w1 = *(uint32_t*)&u1;
        uint32_t w2 = *(uint32_t*)&u2, w3 = *(uint32_t*)&u3;
        uint32_t p0 = __shfl_xor_sync(0xffffffffu, w0, 16);
        uint32_t p1 = __shfl_xor_sync(0xffffffffu, w1, 16);
        uint32_t p2 = __shfl_xor_sync(0xffffffffu, w2, 16);
        uint32_t p3 = __shfl_xor_sync(0xffffffffu, w3, 16);
        uint4 o;
        int c;
        if (lane < 16) {
            c = 2 * (lane & 15);
            o.x = w0; o.y = w1; o.z = p0; o.w = p1;
        } else {
            c = 2 * (lane & 15) + 1;
            o.x = p2; o.y = p3; o.z = w2; o.w = w3;
        }
        ((uint4*)g_ypow)[(size_t)bv * 64 + warp * 32 + c] = o;
    }
}

// ---------------------------------------------------------------------------
// Kernel 2: out = ypow * W^T + bias, relu.  fp16 m16n8k16 mma.  CTA 256 thr,
// tile 128m x 128n, KT=32 halves, 4-stage cp.async pipeline, XOR swizzle,
// ldmatrix.x4 frags.  Warp = 32m x 64n.  (unchanged from R10)
// ---------------------------------------------------------------------------
#define KT     32
#define NKT    (K2 / KT)        // 16
#define M_BLK  128
#define N_BLK  128

__global__ __launch_bounds__(256, 2)
void out_gemm_kernel(const float* __restrict__ bias,
                     float* __restrict__ out)
{
    __shared__ uint32_t sA[4][M_BLK * 16];
    __shared__ uint32_t sB[4][N_BLK * 16];

    const int tid  = threadIdx.x;
    const int warp = tid >> 5;
    const int lane = tid & 31;
    const int g    = lane >> 2;
    const int tig  = lane & 3;
    const int wm   = warp >> 1;
    const int wn   = warp & 1;
    const int m0   = blockIdx.x * M_BLK;
    const int lrow = lane & 15;
    const int lch  = lane >> 4;

    const __half* yp = g_ypow;

    float acc[2][8][4];
    #pragma unroll
    for (int a = 0; a < 2; ++a)
        #pragma unroll
        for (int b = 0; b < 8; ++b)
            #pragma unroll
            for (int c = 0; c < 4; ++c) acc[a][b][c] = 0.0f;

    auto stage = [&](int kt, int st) {
        #pragma unroll
        for (int i = 0; i < 2; ++i) {
            int id = tid + i * 256;
            int row = id >> 2, c = id & 3;
            cp_async16(smem_u32(&sA[st][swz(row, c)]),
                       yp + (size_t)(m0 + row) * K2 + kt * KT + c * 8);
        }
        #pragma unroll
        for (int i = 0; i < 2; ++i) {
            int id = tid + i * 256;
            int row = id >> 2, c = id & 3;
            cp_async16(smem_u32(&sB[st][swz(row, c)]),
                       g_W + (size_t)row * K2 + kt * KT + c * 8);
        }
        asm volatile("cp.async.commit_group;");
    };

    stage(0, 0);
    stage(1, 1);
    stage(2, 2);

    for (int kt = 0; kt < NKT; ++kt) {
        asm volatile("cp.async.wait_group 2;");
        __syncthreads();
        if (kt + 3 < NKT) stage(kt + 3, (kt + 3) & 3);
        else asm volatile("cp.async.commit_group;");
        const int st = kt & 3;

        #pragma unroll
        for (int ks = 0; ks < 2; ++ks) {
            const int ch = ks * 2 + lch;
            uint32_t a[2][4];
            #pragma unroll
            for (int mi = 0; mi < 2; ++mi) {
                int row = wm * 32 + mi * 16 + lrow;
                ldsm_x4(a[mi], smem_u32(&sA[st][swz(row, ch)]));
            }
            uint32_t b[4][4];
            #pragma unroll
            for (int p = 0; p < 4; ++p) {
                int row = wn * 64 + p * 16 + lrow;
                ldsm_x4(b[p], smem_u32(&sB[st][swz(row, ch)]));
            }
            #pragma unroll
            for (int p = 0; p < 4; ++p) {
                mma_f16(acc[0][2*p][0], acc[0][2*p][1], acc[0][2*p][2], acc[0][2*p][3],
                        a[0][0], a[0][1], a[0][2], a[0][3], b[p][0], b[p][2]);
                mma_f16(acc[0][2*p+1][0], acc[0][2*p+1][1], acc[0][2*p+1][2], acc[0][2*p+1][3],
                        a[0][0], a[0][1], a[0][2], a[0][3], b[p][1], b[p][3]);
                mma_f16(acc[1][2*p][0], acc[1][2*p][1], acc[1][2*p][2], acc[1][2*p][3],
                        a[1][0], a[1][1], a[1][2], a[1][3], b[p][0], b[p][2]);
                mma_f16(acc[1][2*p+1][0], acc[1][2*p+1][1], acc[1][2*p+1][2], acc[1][2*p+1][3],
                        a[1][0], a[1][1], a[1][2], a[1][3], b[p][1], b[p][3]);
            }
        }
    }

    #pragma unroll
    for (int nt = 0; nt < 8; ++nt) {
        const int col = wn * 64 + nt * 8 + 2 * tig;
        const float b0 = __ldg(&bias[col]);
        const float b1 = __ldg(&bias[col + 1]);
        #pragma unroll
        for (int mi = 0; mi < 2; ++mi) {
            const int row = m0 + wm * 32 + mi * 16 + g;
            float2 v0, v1;
            v0.x = fmaxf(acc[mi][nt][0] + b0, 0.0f);
            v0.y = fmaxf(acc[mi][nt][1] + b1, 0.0f);
            v1.x = fmaxf(acc[mi][nt][2] + b0, 0.0f);
            v1.y = fmaxf(acc[mi][nt][3] + b1, 0.0f);
            *(float2*)(out + (size_t)row * COUT + col)       = v0;
            *(float2*)(out + (size_t)(row + 8) * COUT + col) = v1;
        }
    }
}

extern "C" void kernel_launch(void* const* d_in, const int* in_sizes, int n_in,
                              void* d_out, int out_size)
{
    const float* signal = (const float*)d_in[0];
    const int*   pidx   = (const int*)  d_in[1];
    const float* convk  = (const float*)d_in[2];
    const float* W      = (const float*)d_in[3];
    const float* bias   = (const float*)d_in[4];
    float* out = (float*)d_out;

    sig2h_kernel<<<B_ * V_ * CIN / 4 / 256, 256>>>(signal);
    ypow_kernel<<<BV, 64>>>(g_S16, pidx, convk, W);
    out_gemm_kernel<<<BV / M_BLK, 256>>>(bias, out);
}

// round 12
// speedup vs baseline: 1.5550x; 1.0876x over previous
#include <cuda_runtime.h>
#include <cuda_fp16.h>
#include <cstdint>

#define B_    8
#define V_    4096
#define P_    32
#define CIN   64
#define COUT  128
#define BV    (B_ * V_)      // 32768
#define K2    512

// ypow [BV][K2] scratch in fp16, k = c*8 + r*4 + l (matches W flattening).
__device__ __half g_ypow[(size_t)BV * K2];
// W pre-converted to fp16 (cvt prologue)
__device__ __half g_W[(size_t)COUT * K2];
// signal pre-converted to fp16 (cvt prologue)
__device__ __half g_S16[(size_t)B_ * V_ * CIN];

__device__ __forceinline__ void mma_f16(float& d0, float& d1, float& d2, float& d3,
                                        uint32_t a0, uint32_t a1, uint32_t a2, uint32_t a3,
                                        uint32_t b0, uint32_t b1) {
    asm volatile(
        "mma.sync.aligned.m16n8k16.row.col.f32.f16.f16.f32 "
        "{%0,%1,%2,%3}, {%4,%5,%6,%7}, {%8,%9}, {%0,%1,%2,%3};"
        : "+f"(d0), "+f"(d1), "+f"(d2), "+f"(d3)
        : "r"(a0), "r"(a1), "r"(a2), "r"(a3), "r"(b0), "r"(b1));
}

__device__ __forceinline__ void ldsm_x4(uint32_t* r, uint32_t addr) {
    asm volatile("ldmatrix.sync.aligned.m8n8.x4.shared.b16 {%0,%1,%2,%3}, [%4];"
        : "=r"(r[0]), "=r"(r[1]), "=r"(r[2]), "=r"(r[3]) : "r"(addr));
}

__device__ __forceinline__ void ldsm_x4_t(uint32_t* r, uint32_t addr) {
    asm volatile("ldmatrix.sync.aligned.m8n8.x4.trans.shared.b16 {%0,%1,%2,%3}, [%4];"
        : "=r"(r[0]), "=r"(r[1]), "=r"(r[2]), "=r"(r[3]) : "r"(addr));
}

__device__ __forceinline__ float sqclip(float x) {
    return sqrtf(fmaxf(x, 1e-4f));
}

__device__ __forceinline__ uint32_t smem_u32(const void* p) {
    return (uint32_t)__cvta_generic_to_shared(p);
}

__device__ __forceinline__ void cp_async16(uint32_t dst, const void* src) {
    asm volatile("cp.async.cg.shared.global [%0], [%1], 16;" :: "r"(dst), "l"(src));
}

// XOR swizzle for tiles with 16-word (64B) rows: chunk c in 0..3
__device__ __forceinline__ int swz(int row, int c) {
    return row * 16 + ((c ^ ((row >> 1) & 3)) << 2);
}

// pack 8 floats (two float4) -> 4 half2 words
__device__ __forceinline__ uint4 pack8h(float4 v0, float4 v1) {
    __half2 h0 = __floats2half2_rn(v0.x, v0.y);
    __half2 h1 = __floats2half2_rn(v0.z, v0.w);
    __half2 h2 = __floats2half2_rn(v1.x, v1.y);
    __half2 h3 = __floats2half2_rn(v1.z, v1.w);
    uint4 u;
    u.x = *(uint32_t*)&h0; u.y = *(uint32_t*)&h1;
    u.z = *(uint32_t*)&h2; u.w = *(uint32_t*)&h3;
    return u;
}

// ---------------------------------------------------------------------------
// Prologue: signal (CTAs 0..255) and W (CTAs 256..263) fp32 -> fp16.
// 8 float4 per thread, coalesced.
// ---------------------------------------------------------------------------
__global__ __launch_bounds__(256)
void cvt_kernel(const float* __restrict__ signal, const float* __restrict__ W)
{
    const int cta = blockIdx.x;
    const float4* src;
    uint2* dst;
    int base;
    if (cta < 256) {
        src = (const float4*)signal;
        dst = (uint2*)g_S16;
        base = cta * 2048 + threadIdx.x;
    } else {
        src = (const float4*)W;
        dst = (uint2*)g_W;
        base = (cta - 256) * 2048 + threadIdx.x;
    }
    #pragma unroll
    for (int j = 0; j < 8; ++j) {
        int i = base + j * 256;
        float4 v = src[i];
        __half2 h0 = __floats2half2_rn(v.x, v.y);
        __half2 h1 = __floats2half2_rn(v.z, v.w);
        uint2 u;
        u.x = *(uint32_t*)&h0; u.y = *(uint32_t*)&h1;
        dst[i] = u;
    }
}

// ---------------------------------------------------------------------------
// Kernel 1: CTA = 64 threads = 2 warps = ONE bv, full fp16 datapath.
// D[m=rn 32][n=c'] = ck^T * S, fp16 m16n8k16 mma; warp h owns c-half h.
// S gathered via cp.async (overlaps with ck convert/stage). Bounce [c2][rn]
// half2 stride 36.  Incremental-register epilogue, r-half shuffle exchange,
// coalesced uint4 STG.
// ---------------------------------------------------------------------------
#define YB_STR 36   // bounce row stride in words (half2 units)

__global__ __launch_bounds__(64, 16)
void ypow_kernel(const int*   __restrict__ pidx,
                 const float* __restrict__ convk)
{
    __shared__ uint32_t sCK[32 * 16];     // fp16 [p][rn 32h] swizzled, 2KB
    __shared__ uint32_t sSh[2][640];      // per-warp: S tile (512w) / bounce (576w)

    const int tid  = threadIdx.x;
    const int warp = tid >> 5;      // c-half
    const int lane = tid & 31;
    const int bv   = blockIdx.x;
    const int g    = lane >> 2;
    const int tig  = lane & 3;
    const int grp  = lane >> 3;     // ldsm address group
    const int gi   = lane & 7;

    // lane p = lane: gathered signal row base (in halves)
    const int2 ip = ((const int2*)pidx)[bv * P_ + lane];
    const int base = (ip.x * V_ + ip.y) * CIN;

    // Issue S-half gather via cp.async FIRST (overlaps with ck staging below)
    {
        uint32_t* sS = sSh[warp];
        #pragma unroll
        for (int j = 0; j < 4; ++j) {
            int id = j * 32 + lane;
            int row = id >> 2, c = id & 3;
            int bp = __shfl_sync(0xffffffffu, base, row);
            cp_async16(smem_u32(&sS[swz(row, c)]),
                       g_S16 + bp + warp * 32 + c * 8);
        }
        asm volatile("cp.async.commit_group;");
    }

    // Stage ck [p][rn] -> fp16 swizzled: 128 chunks, 2 per thread
    {
        const float* ck = convk + (size_t)bv * 1024;
        #pragma unroll
        for (int it = 0; it < 2; ++it) {
            int id = tid + it * 64;
            int row = id >> 2, c = id & 3;
            const float4* src = (const float4*)(ck + row * 32 + c * 8);
            *(uint4*)&sCK[swz(row, c)] = pack8h(src[0], src[1]);
        }
    }
    asm volatile("cp.async.wait_group 0;");
    __syncthreads();   // sCK written by both warps; S tiles landed

    const uint32_t sCKb = smem_u32(sCK);
    const uint32_t sSb  = smem_u32(sSh[warp]);

    // D[m=rn 32][n = its 32 c']: 2 mt x 4 nt x 2 ks (k16 each)
    float acc[2][4][4];
    #pragma unroll
    for (int i = 0; i < 2; ++i)
        #pragma unroll
        for (int j = 0; j < 4; ++j)
            #pragma unroll
            for (int e = 0; e < 4; ++e) acc[i][j][e] = 0.0f;

    #pragma unroll
    for (int ks = 0; ks < 2; ++ks) {
        uint32_t a[2][4];
        #pragma unroll
        for (int mt = 0; mt < 2; ++mt) {
            int row = ks * 16 + (grp >> 1) * 8 + gi;
            int ch  = mt * 2 + (grp & 1);
            ldsm_x4_t(a[mt], sCKb + 4 * swz(row, ch));
        }
        uint32_t b[2][4];
        #pragma unroll
        for (int ntp = 0; ntp < 2; ++ntp) {
            int row = ks * 16 + (grp & 1) * 8 + gi;
            int ch  = ntp * 2 + (grp >> 1);
            ldsm_x4_t(b[ntp], sSb + 4 * swz(row, ch));
        }
        #pragma unroll
        for (int mt = 0; mt < 2; ++mt)
            #pragma unroll
            for (int nt = 0; nt < 4; ++nt) {
                uint32_t b0 = b[nt >> 1][(nt & 1) * 2];
                uint32_t b1 = b[nt >> 1][(nt & 1) * 2 + 1];
                mma_f16(acc[mt][nt][0], acc[mt][nt][1], acc[mt][nt][2], acc[mt][nt][3],
                        a[mt][0], a[mt][1], a[mt][2], a[mt][3], b0, b1);
            }
    }
    __syncwarp();   // done reading own sS half; overlay it with bounce

    // acc -> bounce [c2][rn] half2 (c-pair packed), 16 STS.32, conflict-free.
    uint32_t* sY = sSh[warp];
    #pragma unroll
    for (int mt = 0; mt < 2; ++mt) {
        #pragma unroll
        for (int nt = 0; nt < 4; ++nt) {
            const int c2 = nt * 4 + tig;
            const int rn = mt * 16 + g;
            __half2 h01 = __floats2half2_rn(acc[mt][nt][0], acc[mt][nt][1]);
            __half2 h23 = __floats2half2_rn(acc[mt][nt][2], acc[mt][nt][3]);
            sY[c2 * YB_STR + rn]     = *(uint32_t*)&h01;
            sY[c2 * YB_STR + rn + 8] = *(uint32_t*)&h23;
        }
    }
    __syncwarp();

    // Epilogue: lane = (c2 = lane&15, r = lane>>4).  4x LDS.128, incremental
    // square-accumulate into 8 l-buckets (low register pressure); sqrt; pack;
    // r-half exchange via shfl.xor(16); coalesced uint4 STG.
    {
        const uint32_t* rp = sY + (lane & 15) * YB_STR + (lane >> 4) * 16;
        float s0[4] = {0.f, 0.f, 0.f, 0.f};
        float s1[4] = {0.f, 0.f, 0.f, 0.f};
        #pragma unroll
        for (int j = 0; j < 4; ++j) {
            uint4 q = *(const uint4*)&rp[j * 4];
            uint32_t w[4] = {q.x, q.y, q.z, q.w};
            #pragma unroll
            for (int e = 0; e < 4; ++e) {
                const int n = j * 4 + e;
                const int l = (n == 0) ? 0 : (n <= 3) ? 1 : (n <= 8) ? 2 : 3;
                float2 f = __half22float2(*(const __half2*)&w[e]);
                s0[l] += f.x * f.x;
                s1[l] += f.y * f.y;
            }
        }
        __half2 u0 = __floats2half2_rn(sqclip(s0[0]), sqclip(s0[1]));
        __half2 u1 = __floats2half2_rn(sqclip(s0[2]), sqclip(s0[3]));
        __half2 u2 = __floats2half2_rn(sqclip(s1[0]), sqclip(s1[1]));
        __half2 u3 = __floats2half2_rn(sqclip(s1[2]), sqclip(s1[3]));
        uint32_t w0 = *(uint32_t*)&u0, w1 = *(uint32_t*)&u1;
        uint32_t w2 = *(uint32_t*)&u2, w3 = *(uint32_t*)&u3;
        uint32_t p0 = __shfl_xor_sync(0xffffffffu, w0, 16);
        uint32_t p1 = __shfl_xor_sync(0xffffffffu, w1, 16);
        uint32_t p2 = __shfl_xor_sync(0xffffffffu, w2, 16);
        uint32_t p3 = __shfl_xor_sync(0xffffffffu, w3, 16);
        uint4 o;
        int c;
        if (lane < 16) {
            c = 2 * (lane & 15);
            o.x = w0; o.y = w1; o.z = p0; o.w = p1;
        } else {
            c = 2 * (lane & 15) + 1;
            o.x = p2; o.y = p3; o.z = w2; o.w = w3;
        }
        ((uint4*)g_ypow)[(size_t)bv * 64 + warp * 32 + c] = o;
    }
}

// ---------------------------------------------------------------------------
// Kernel 2: out = ypow * W^T + bias, relu.  fp16 m16n8k16 mma.  CTA 256 thr,
// tile 128m x 128n, KT=32 halves, 4-stage cp.async pipeline, XOR swizzle,
// ldmatrix.x4 frags.  Warp = 32m x 64n.  (unchanged)
// ---------------------------------------------------------------------------
#define KT     32
#define NKT    (K2 / KT)        // 16
#define M_BLK  128
#define N_BLK  128

__global__ __launch_bounds__(256, 2)
void out_gemm_kernel(const float* __restrict__ bias,
                     float* __restrict__ out)
{
    __shared__ uint32_t sA[4][M_BLK * 16];
    __shared__ uint32_t sB[4][N_BLK * 16];

    const int tid  = threadIdx.x;
    const int warp = tid >> 5;
    const int lane = tid & 31;
    const int g    = lane >> 2;
    const int tig  = lane & 3;
    const int wm   = warp >> 1;
    const int wn   = warp & 1;
    const int m0   = blockIdx.x * M_BLK;
    const int lrow = lane & 15;
    const int lch  = lane >> 4;

    const __half* yp = g_ypow;

    float acc[2][8][4];
    #pragma unroll
    for (int a = 0; a < 2; ++a)
        #pragma unroll
        for (int b = 0; b < 8; ++b)
            #pragma unroll
            for (int c = 0; c < 4; ++c) acc[a][b][c] = 0.0f;

    auto stage = [&](int kt, int st) {
        #pragma unroll
        for (int i = 0; i < 2; ++i) {
            int id = tid + i * 256;
            int row = id >> 2, c = id & 3;
            cp_async16(smem_u32(&sA[st][swz(row, c)]),
                       yp + (size_t)(m0 + row) * K2 + kt * KT + c * 8);
        }
        #pragma unroll
        for (int i = 0; i < 2; ++i) {
            int id = tid + i * 256;
            int row = id >> 2, c = id & 3;
            cp_async16(smem_u32(&sB[st][swz(row, c)]),
                       g_W + (size_t)row * K2 + kt * KT + c * 8);
        }
        asm volatile("cp.async.commit_group;");
    };

    stage(0, 0);
    stage(1, 1);
    stage(2, 2);

    for (int kt = 0; kt < NKT; ++kt) {
        asm volatile("cp.async.wait_group 2;");
        __syncthreads();
        if (kt + 3 < NKT) stage(kt + 3, (kt + 3) & 3);
        else asm volatile("cp.async.commit_group;");
        const int st = kt & 3;

        #pragma unroll
        for (int ks = 0; ks < 2; ++ks) {
            const int ch = ks * 2 + lch;
            uint32_t a[2][4];
            #pragma unroll
            for (int mi = 0; mi < 2; ++mi) {
                int row = wm * 32 + mi * 16 + lrow;
                ldsm_x4(a[mi], smem_u32(&sA[st][swz(row, ch)]));
            }
            uint32_t b[4][4];
            #pragma unroll
            for (int p = 0; p < 4; ++p) {
                int row = wn * 64 + p * 16 + lrow;
                ldsm_x4(b[p], smem_u32(&sB[st][swz(row, ch)]));
            }
            #pragma unroll
            for (int p = 0; p < 4; ++p) {
                mma_f16(acc[0][2*p][0], acc[0][2*p][1], acc[0][2*p][2], acc[0][2*p][3],
                        a[0][0], a[0][1], a[0][2], a[0][3], b[p][0], b[p][2]);
                mma_f16(acc[0][2*p+1][0], acc[0][2*p+1][1], acc[0][2*p+1][2], acc[0][2*p+1][3],
                        a[0][0], a[0][1], a[0][2], a[0][3], b[p][1], b[p][3]);
                mma_f16(acc[1][2*p][0], acc[1][2*p][1], acc[1][2*p][2], acc[1][2*p][3],
                        a[1][0], a[1][1], a[1][2], a[1][3], b[p][0], b[p][2]);
                mma_f16(acc[1][2*p+1][0], acc[1][2*p+1][1], acc[1][2*p+1][2], acc[1][2*p+1][3],
                        a[1][0], a[1][1], a[1][2], a[1][3], b[p][1], b[p][3]);
            }
        }
    }

    #pragma unroll
    for (int nt = 0; nt < 8; ++nt) {
        const int col = wn * 64 + nt * 8 + 2 * tig;
        const float b0 = __ldg(&bias[col]);
        const float b1 = __ldg(&bias[col + 1]);
        #pragma unroll
        for (int mi = 0; mi < 2; ++mi) {
            const int row = m0 + wm * 32 + mi * 16 + g;
            float2 v0, v1;
            v0.x = fmaxf(acc[mi][nt][0] + b0, 0.0f);
            v0.y = fmaxf(acc[mi][nt][1] + b1, 0.0f);
            v1.x = fmaxf(acc[mi][nt][2] + b0, 0.0f);
            v1.y = fmaxf(acc[mi][nt][3] + b1, 0.0f);
            *(float2*)(out + (size_t)row * COUT + col)       = v0;
            *(float2*)(out + (size_t)(row + 8) * COUT + col) = v1;
        }
    }
}

extern "C" void kernel_launch(void* const* d_in, const int* in_sizes, int n_in,
                              void* d_out, int out_size)
{
    const float* signal = (const float*)d_in[0];
    const int*   pidx   = (const int*)  d_in[1];
    const float* convk  = (const float*)d_in[2];
    const float* W      = (const float*)d_in[3];
    const float* bias   = (const float*)d_in[4];
    float* out = (float*)d_out;

    cvt_kernel<<<264, 256>>>(signal, W);
    ypow_kernel<<<BV, 64>>>(pidx, convk);
    out_gemm_kernel<<<BV / M_BLK, 256>>>(bias, out);
}